// round 1
// baseline (speedup 1.0000x reference)
#include <cuda_runtime.h>
#include <cuda_bf16.h>
#include <math.h>

// Problem constants
#define BATCH 4
#define LSEQ  2048
#define SSEQ  2048
#define DMODEL 1024
#define NHEAD 16
#define EDIM  64   // head dim
#define MTOT  (BATCH * LSEQ)   // 8192 rows for projection GEMMs

// ---------------------------------------------------------------------------
// Scratch (device globals; no runtime allocation allowed)
// ---------------------------------------------------------------------------
__device__ float g_q[MTOT * DMODEL];
__device__ float g_k[MTOT * DMODEL];
__device__ float g_v[MTOT * DMODEL];
__device__ float g_attn[MTOT * DMODEL];

// ---------------------------------------------------------------------------
// SGEMM: C[M,N] = A[M,K] @ W[K,N] + bias, N=K=1024, M=8192
// 128x128 tile, BK=16, 256 threads, 8x8 micro-tile
// ---------------------------------------------------------------------------
#define GM 128
#define GN 128
#define GK 16
#define GEMM_N 1024
#define GEMM_K 1024

__global__ __launch_bounds__(256) void gemm_bias_kernel(
    const float* __restrict__ A, const float* __restrict__ W,
    const float* __restrict__ bias, float* __restrict__ C)
{
    __shared__ float a_s[GK][GM + 4];  // transposed A tile, padded
    __shared__ float w_s[GK][GN];

    const int tid = threadIdx.x;
    const int tx = tid & 15;         // 0..15 -> N
    const int ty = tid >> 4;         // 0..15 -> M
    const int m_base = blockIdx.y * GM;
    const int n_base = blockIdx.x * GN;

    // global-load mappings
    const int arow  = tid >> 2;          // 0..63
    const int acol4 = (tid & 3) * 4;     // 0,4,8,12
    const int wrow  = tid >> 5;          // 0..7
    const int wcol4 = (tid & 31) * 4;    // 0..124

    float acc[8][8];
    #pragma unroll
    for (int i = 0; i < 8; i++)
        #pragma unroll
        for (int j = 0; j < 8; j++) acc[i][j] = 0.0f;

    for (int k0 = 0; k0 < GEMM_K; k0 += GK) {
        // load A tile (transpose into smem)
        #pragma unroll
        for (int t = 0; t < 2; t++) {
            const int r = arow + t * 64;
            float4 av = *(const float4*)(A + (size_t)(m_base + r) * GEMM_K + k0 + acol4);
            a_s[acol4 + 0][r] = av.x;
            a_s[acol4 + 1][r] = av.y;
            a_s[acol4 + 2][r] = av.z;
            a_s[acol4 + 3][r] = av.w;
        }
        // load W tile (natural layout)
        #pragma unroll
        for (int t = 0; t < 2; t++) {
            const int r = wrow + t * 8;
            float4 wv = *(const float4*)(W + (size_t)(k0 + r) * GEMM_N + n_base + wcol4);
            *(float4*)&w_s[r][wcol4] = wv;
        }
        __syncthreads();

        #pragma unroll
        for (int k = 0; k < GK; k++) {
            float4 a0 = *(const float4*)&a_s[k][ty * 4];
            float4 a1 = *(const float4*)&a_s[k][ty * 4 + 64];
            float4 b0 = *(const float4*)&w_s[k][tx * 4];
            float4 b1 = *(const float4*)&w_s[k][tx * 4 + 64];
            const float ar[8] = {a0.x, a0.y, a0.z, a0.w, a1.x, a1.y, a1.z, a1.w};
            const float bc[8] = {b0.x, b0.y, b0.z, b0.w, b1.x, b1.y, b1.z, b1.w};
            #pragma unroll
            for (int i = 0; i < 8; i++)
                #pragma unroll
                for (int j = 0; j < 8; j++)
                    acc[i][j] = fmaf(ar[i], bc[j], acc[i][j]);
        }
        __syncthreads();
    }

    // epilogue with bias
    float4 blo = *(const float4*)(bias + n_base + tx * 4);
    float4 bhi = *(const float4*)(bias + n_base + tx * 4 + 64);
    #pragma unroll
    for (int i = 0; i < 8; i++) {
        const int m = m_base + ty * 4 + (i & 3) + (i >> 2) * 64;
        float4 lo, hi;
        lo.x = acc[i][0] + blo.x; lo.y = acc[i][1] + blo.y;
        lo.z = acc[i][2] + blo.z; lo.w = acc[i][3] + blo.w;
        hi.x = acc[i][4] + bhi.x; hi.y = acc[i][5] + bhi.y;
        hi.z = acc[i][6] + bhi.z; hi.w = acc[i][7] + bhi.w;
        *(float4*)(C + (size_t)m * GEMM_N + n_base + tx * 4)      = lo;
        *(float4*)(C + (size_t)m * GEMM_N + n_base + tx * 4 + 64) = hi;
    }
}

// ---------------------------------------------------------------------------
// Flash-attention (fp32): per (b,h), 64 query rows per block, tile S by 64.
// smem: q_s[e][r], k_s[e][j] (reused as p_s[j][r]), v_s[j][c]  -> exactly 48KB
// 256 threads: (ty,tx) in 16x16, each owns 4 rows x 4 cols micro-tile.
// ---------------------------------------------------------------------------
__global__ __launch_bounds__(256) void attn_kernel(
    const float* __restrict__ gq, const float* __restrict__ gk,
    const float* __restrict__ gv, float* __restrict__ go)
{
    __shared__ float q_s[64 * 64];   // [e][r]
    __shared__ float k_s[64 * 64];   // [e][j]  -> reused as p_s[j][r]
    __shared__ float v_s[64 * 64];   // [j][c]

    const int bh = blockIdx.y;
    const int b = bh / NHEAD;
    const int h = bh % NHEAD;
    const int q0 = blockIdx.x * 64;
    const int tid = threadIdx.x;
    const int tx = tid & 15;
    const int ty = tid >> 4;

    const float* qbase = gq + (size_t)b * LSEQ * DMODEL + h * EDIM;
    const float* kbase = gk + (size_t)b * SSEQ * DMODEL + h * EDIM;
    const float* vbase = gv + (size_t)b * SSEQ * DMODEL + h * EDIM;

    // load Q tile transposed: q_s[e][r]
    {
        const int r  = tid & 63;
        const int e0 = (tid >> 6) * 16;
        const float4* src = (const float4*)(qbase + (size_t)(q0 + r) * DMODEL + e0);
        #pragma unroll
        for (int t = 0; t < 4; t++) {
            float4 vq = src[t];
            q_s[(e0 + t * 4 + 0) * 64 + r] = vq.x;
            q_s[(e0 + t * 4 + 1) * 64 + r] = vq.y;
            q_s[(e0 + t * 4 + 2) * 64 + r] = vq.z;
            q_s[(e0 + t * 4 + 3) * 64 + r] = vq.w;
        }
    }

    float m[4], l[4], acc[4][4];
    #pragma unroll
    for (int i = 0; i < 4; i++) {
        m[i] = -1e30f; l[i] = 0.0f;
        #pragma unroll
        for (int j = 0; j < 4; j++) acc[i][j] = 0.0f;
    }

    for (int s0 = 0; s0 < SSEQ; s0 += 64) {
        __syncthreads();  // previous-iteration AV reads done before reload
        // K tile transposed: k_s[e][j]
        {
            const int j  = tid & 63;
            const int e0 = (tid >> 6) * 16;
            const float4* src = (const float4*)(kbase + (size_t)(s0 + j) * DMODEL + e0);
            #pragma unroll
            for (int t = 0; t < 4; t++) {
                float4 vk = src[t];
                k_s[(e0 + t * 4 + 0) * 64 + j] = vk.x;
                k_s[(e0 + t * 4 + 1) * 64 + j] = vk.y;
                k_s[(e0 + t * 4 + 2) * 64 + j] = vk.z;
                k_s[(e0 + t * 4 + 3) * 64 + j] = vk.w;
            }
            // V tile natural: v_s[j][c]
            const int jr = tid >> 2;          // 0..63
            const int c0 = (tid & 3) * 16;    // 0,16,32,48
            const float4* vsrc = (const float4*)(vbase + (size_t)(s0 + jr) * DMODEL + c0);
            float4* vdst = (float4*)(v_s + jr * 64 + c0);
            #pragma unroll
            for (int t = 0; t < 4; t++) vdst[t] = vsrc[t];
        }
        __syncthreads();

        // scores: sc[i][j2] = sum_e Q[r][e] * K[j][e], scaled
        float sc[4][4];
        #pragma unroll
        for (int i = 0; i < 4; i++)
            #pragma unroll
            for (int j = 0; j < 4; j++) sc[i][j] = 0.0f;

        #pragma unroll 16
        for (int e = 0; e < 64; e++) {
            float4 qv = *(const float4*)(q_s + e * 64 + ty * 4);
            float4 kv = *(const float4*)(k_s + e * 64 + tx * 4);
            const float qr[4] = {qv.x, qv.y, qv.z, qv.w};
            const float kc[4] = {kv.x, kv.y, kv.z, kv.w};
            #pragma unroll
            for (int i = 0; i < 4; i++)
                #pragma unroll
                for (int j = 0; j < 4; j++)
                    sc[i][j] = fmaf(qr[i], kc[j], sc[i][j]);
        }

        // online softmax update
        float p[4][4];
        #pragma unroll
        for (int i = 0; i < 4; i++) {
            float tm = fmaxf(fmaxf(sc[i][0], sc[i][1]), fmaxf(sc[i][2], sc[i][3])) * 0.125f;
            // reduce max across the 16 tx-threads of this row group
            #pragma unroll
            for (int off = 1; off < 16; off <<= 1)
                tm = fmaxf(tm, __shfl_xor_sync(0xffffffffu, tm, off));
            const float newm = fmaxf(m[i], tm);
            const float corr = __expf(m[i] - newm);
            float rs = 0.0f;
            #pragma unroll
            for (int j = 0; j < 4; j++) {
                p[i][j] = __expf(sc[i][j] * 0.125f - newm);
                rs += p[i][j];
            }
            #pragma unroll
            for (int off = 1; off < 16; off <<= 1)
                rs += __shfl_xor_sync(0xffffffffu, rs, off);
            l[i] = l[i] * corr + rs;
            m[i] = newm;
            #pragma unroll
            for (int j = 0; j < 4; j++) acc[i][j] *= corr;
        }

        __syncthreads();  // all threads done reading k_s
        // store P transposed into k_s: p_s[j][r]
        #pragma unroll
        for (int i = 0; i < 4; i++)
            #pragma unroll
            for (int j = 0; j < 4; j++)
                k_s[(tx * 4 + j) * 64 + (ty * 4 + i)] = p[i][j];
        __syncthreads();

        // AV: acc[i][c] += sum_j P[r][j] * V[j][c]
        #pragma unroll 16
        for (int j = 0; j < 64; j++) {
            float4 pv = *(const float4*)(k_s + j * 64 + ty * 4);
            float4 vv = *(const float4*)(v_s + j * 64 + tx * 4);
            const float pr[4] = {pv.x, pv.y, pv.z, pv.w};
            const float vc[4] = {vv.x, vv.y, vv.z, vv.w};
            #pragma unroll
            for (int i = 0; i < 4; i++)
                #pragma unroll
                for (int c = 0; c < 4; c++)
                    acc[i][c] = fmaf(pr[i], vc[c], acc[i][c]);
        }
    }

    // epilogue: normalize and write [B,L,H,E] layout (== [8192,1024] row-major)
    #pragma unroll
    for (int i = 0; i < 4; i++) {
        const float inv = 1.0f / l[i];
        const int r = ty * 4 + i;
        float4 o;
        o.x = acc[i][0] * inv; o.y = acc[i][1] * inv;
        o.z = acc[i][2] * inv; o.w = acc[i][3] * inv;
        *(float4*)(go + (size_t)(b * LSEQ + q0 + r) * DMODEL + h * EDIM + tx * 4) = o;
    }
}

// ---------------------------------------------------------------------------
// launch
// ---------------------------------------------------------------------------
extern "C" void kernel_launch(void* const* d_in, const int* in_sizes, int n_in,
                              void* d_out, int out_size)
{
    (void)in_sizes; (void)n_in; (void)out_size;
    const float* queries = (const float*)d_in[0];
    const float* keys    = (const float*)d_in[1];
    const float* values  = (const float*)d_in[2];
    const float* Wq = (const float*)d_in[3];
    const float* bq = (const float*)d_in[4];
    const float* Wk = (const float*)d_in[5];
    const float* bk = (const float*)d_in[6];
    const float* Wv = (const float*)d_in[7];
    const float* bv = (const float*)d_in[8];
    const float* Wo = (const float*)d_in[9];
    const float* bo = (const float*)d_in[10];
    float* out = (float*)d_out;

    float *q, *k, *v, *attn;
    cudaGetSymbolAddress((void**)&q,    g_q);
    cudaGetSymbolAddress((void**)&k,    g_k);
    cudaGetSymbolAddress((void**)&v,    g_v);
    cudaGetSymbolAddress((void**)&attn, g_attn);

    dim3 gemm_grid(GEMM_N / GN, MTOT / GM);   // (8, 64)
    gemm_bias_kernel<<<gemm_grid, 256>>>(queries, Wq, bq, q);
    gemm_bias_kernel<<<gemm_grid, 256>>>(keys,    Wk, bk, k);
    gemm_bias_kernel<<<gemm_grid, 256>>>(values,  Wv, bv, v);

    dim3 attn_grid(LSEQ / 64, BATCH * NHEAD); // (32, 64)
    attn_kernel<<<attn_grid, 256>>>(q, k, v, attn);

    gemm_bias_kernel<<<gemm_grid, 256>>>(attn, Wo, bo, out);
}

// round 2
// speedup vs baseline: 1.0007x; 1.0007x over previous
#include <cuda_runtime.h>
#include <cuda_bf16.h>
#include <math.h>

// Problem constants
#define BATCH 4
#define LSEQ  2048
#define SSEQ  2048
#define DMODEL 1024
#define NHEAD 16
#define EDIM  64   // head dim
#define MTOT  (BATCH * LSEQ)   // 8192 rows for projection GEMMs

// ---------------------------------------------------------------------------
// Scratch (device globals; no runtime allocation allowed)
// ---------------------------------------------------------------------------
__device__ float g_q[MTOT * DMODEL];
__device__ float g_k[MTOT * DMODEL];
__device__ float g_v[MTOT * DMODEL];
__device__ float g_attn[MTOT * DMODEL];

// ---------------------------------------------------------------------------
// SGEMM: C[M,N] = A[M,K] @ W[K,N] + bias, N=K=1024, M=8192
// 128x128 tile, BK=16, 256 threads, 8x8 micro-tile
// ---------------------------------------------------------------------------
#define GM 128
#define GN 128
#define GK 16
#define GEMM_N 1024
#define GEMM_K 1024

__global__ __launch_bounds__(256) void gemm_bias_kernel(
    const float* __restrict__ A, const float* __restrict__ W,
    const float* __restrict__ bias, float* __restrict__ C)
{
    __shared__ float a_s[GK][GM + 4];  // transposed A tile, padded
    __shared__ float w_s[GK][GN];

    const int tid = threadIdx.x;
    const int tx = tid & 15;         // 0..15 -> N
    const int ty = tid >> 4;         // 0..15 -> M
    const int m_base = blockIdx.y * GM;
    const int n_base = blockIdx.x * GN;

    // global-load mappings
    const int arow  = tid >> 2;          // 0..63
    const int acol4 = (tid & 3) * 4;     // 0,4,8,12
    const int wrow  = tid >> 5;          // 0..7
    const int wcol4 = (tid & 31) * 4;    // 0..124

    float acc[8][8];
    #pragma unroll
    for (int i = 0; i < 8; i++)
        #pragma unroll
        for (int j = 0; j < 8; j++) acc[i][j] = 0.0f;

    for (int k0 = 0; k0 < GEMM_K; k0 += GK) {
        // load A tile (transpose into smem)
        #pragma unroll
        for (int t = 0; t < 2; t++) {
            const int r = arow + t * 64;
            float4 av = *(const float4*)(A + (size_t)(m_base + r) * GEMM_K + k0 + acol4);
            a_s[acol4 + 0][r] = av.x;
            a_s[acol4 + 1][r] = av.y;
            a_s[acol4 + 2][r] = av.z;
            a_s[acol4 + 3][r] = av.w;
        }
        // load W tile (natural layout)
        #pragma unroll
        for (int t = 0; t < 2; t++) {
            const int r = wrow + t * 8;
            float4 wv = *(const float4*)(W + (size_t)(k0 + r) * GEMM_N + n_base + wcol4);
            *(float4*)&w_s[r][wcol4] = wv;
        }
        __syncthreads();

        #pragma unroll
        for (int k = 0; k < GK; k++) {
            float4 a0 = *(const float4*)&a_s[k][ty * 4];
            float4 a1 = *(const float4*)&a_s[k][ty * 4 + 64];
            float4 b0 = *(const float4*)&w_s[k][tx * 4];
            float4 b1 = *(const float4*)&w_s[k][tx * 4 + 64];
            const float ar[8] = {a0.x, a0.y, a0.z, a0.w, a1.x, a1.y, a1.z, a1.w};
            const float bc[8] = {b0.x, b0.y, b0.z, b0.w, b1.x, b1.y, b1.z, b1.w};
            #pragma unroll
            for (int i = 0; i < 8; i++)
                #pragma unroll
                for (int j = 0; j < 8; j++)
                    acc[i][j] = fmaf(ar[i], bc[j], acc[i][j]);
        }
        __syncthreads();
    }

    // epilogue with bias
    float4 blo = *(const float4*)(bias + n_base + tx * 4);
    float4 bhi = *(const float4*)(bias + n_base + tx * 4 + 64);
    #pragma unroll
    for (int i = 0; i < 8; i++) {
        const int m = m_base + ty * 4 + (i & 3) + (i >> 2) * 64;
        float4 lo, hi;
        lo.x = acc[i][0] + blo.x; lo.y = acc[i][1] + blo.y;
        lo.z = acc[i][2] + blo.z; lo.w = acc[i][3] + blo.w;
        hi.x = acc[i][4] + bhi.x; hi.y = acc[i][5] + bhi.y;
        hi.z = acc[i][6] + bhi.z; hi.w = acc[i][7] + bhi.w;
        *(float4*)(C + (size_t)m * GEMM_N + n_base + tx * 4)      = lo;
        *(float4*)(C + (size_t)m * GEMM_N + n_base + tx * 4 + 64) = hi;
    }
}

// ---------------------------------------------------------------------------
// Flash-attention (fp32): per (b,h), 64 query rows per block, tile S by 64.
// smem: q_s[e][r], k_s[e][j] (reused as p_s[j][r]), v_s[j][c]  -> exactly 48KB
// 256 threads: (ty,tx) in 16x16, each owns 4 rows x 4 cols micro-tile.
// ---------------------------------------------------------------------------
__global__ __launch_bounds__(256) void attn_kernel(
    const float* __restrict__ gq, const float* __restrict__ gk,
    const float* __restrict__ gv, float* __restrict__ go)
{
    __shared__ float q_s[64 * 64];   // [e][r]
    __shared__ float k_s[64 * 64];   // [e][j]  -> reused as p_s[j][r]
    __shared__ float v_s[64 * 64];   // [j][c]

    const int bh = blockIdx.y;
    const int b = bh / NHEAD;
    const int h = bh % NHEAD;
    const int q0 = blockIdx.x * 64;
    const int tid = threadIdx.x;
    const int tx = tid & 15;
    const int ty = tid >> 4;

    const float* qbase = gq + (size_t)b * LSEQ * DMODEL + h * EDIM;
    const float* kbase = gk + (size_t)b * SSEQ * DMODEL + h * EDIM;
    const float* vbase = gv + (size_t)b * SSEQ * DMODEL + h * EDIM;

    // load Q tile transposed: q_s[e][r]
    {
        const int r  = tid & 63;
        const int e0 = (tid >> 6) * 16;
        const float4* src = (const float4*)(qbase + (size_t)(q0 + r) * DMODEL + e0);
        #pragma unroll
        for (int t = 0; t < 4; t++) {
            float4 vq = src[t];
            q_s[(e0 + t * 4 + 0) * 64 + r] = vq.x;
            q_s[(e0 + t * 4 + 1) * 64 + r] = vq.y;
            q_s[(e0 + t * 4 + 2) * 64 + r] = vq.z;
            q_s[(e0 + t * 4 + 3) * 64 + r] = vq.w;
        }
    }

    float m[4], l[4], acc[4][4];
    #pragma unroll
    for (int i = 0; i < 4; i++) {
        m[i] = -1e30f; l[i] = 0.0f;
        #pragma unroll
        for (int j = 0; j < 4; j++) acc[i][j] = 0.0f;
    }

    for (int s0 = 0; s0 < SSEQ; s0 += 64) {
        __syncthreads();  // previous-iteration AV reads done before reload
        // K tile transposed: k_s[e][j]
        {
            const int j  = tid & 63;
            const int e0 = (tid >> 6) * 16;
            const float4* src = (const float4*)(kbase + (size_t)(s0 + j) * DMODEL + e0);
            #pragma unroll
            for (int t = 0; t < 4; t++) {
                float4 vk = src[t];
                k_s[(e0 + t * 4 + 0) * 64 + j] = vk.x;
                k_s[(e0 + t * 4 + 1) * 64 + j] = vk.y;
                k_s[(e0 + t * 4 + 2) * 64 + j] = vk.z;
                k_s[(e0 + t * 4 + 3) * 64 + j] = vk.w;
            }
            // V tile natural: v_s[j][c]
            const int jr = tid >> 2;          // 0..63
            const int c0 = (tid & 3) * 16;    // 0,16,32,48
            const float4* vsrc = (const float4*)(vbase + (size_t)(s0 + jr) * DMODEL + c0);
            float4* vdst = (float4*)(v_s + jr * 64 + c0);
            #pragma unroll
            for (int t = 0; t < 4; t++) vdst[t] = vsrc[t];
        }
        __syncthreads();

        // scores: sc[i][j2] = sum_e Q[r][e] * K[j][e], scaled
        float sc[4][4];
        #pragma unroll
        for (int i = 0; i < 4; i++)
            #pragma unroll
            for (int j = 0; j < 4; j++) sc[i][j] = 0.0f;

        #pragma unroll 16
        for (int e = 0; e < 64; e++) {
            float4 qv = *(const float4*)(q_s + e * 64 + ty * 4);
            float4 kv = *(const float4*)(k_s + e * 64 + tx * 4);
            const float qr[4] = {qv.x, qv.y, qv.z, qv.w};
            const float kc[4] = {kv.x, kv.y, kv.z, kv.w};
            #pragma unroll
            for (int i = 0; i < 4; i++)
                #pragma unroll
                for (int j = 0; j < 4; j++)
                    sc[i][j] = fmaf(qr[i], kc[j], sc[i][j]);
        }

        // online softmax update
        float p[4][4];
        #pragma unroll
        for (int i = 0; i < 4; i++) {
            float tm = fmaxf(fmaxf(sc[i][0], sc[i][1]), fmaxf(sc[i][2], sc[i][3])) * 0.125f;
            // reduce max across the 16 tx-threads of this row group
            #pragma unroll
            for (int off = 1; off < 16; off <<= 1)
                tm = fmaxf(tm, __shfl_xor_sync(0xffffffffu, tm, off));
            const float newm = fmaxf(m[i], tm);
            const float corr = __expf(m[i] - newm);
            float rs = 0.0f;
            #pragma unroll
            for (int j = 0; j < 4; j++) {
                p[i][j] = __expf(sc[i][j] * 0.125f - newm);
                rs += p[i][j];
            }
            #pragma unroll
            for (int off = 1; off < 16; off <<= 1)
                rs += __shfl_xor_sync(0xffffffffu, rs, off);
            l[i] = l[i] * corr + rs;
            m[i] = newm;
            #pragma unroll
            for (int j = 0; j < 4; j++) acc[i][j] *= corr;
        }

        __syncthreads();  // all threads done reading k_s
        // store P transposed into k_s: p_s[j][r]
        #pragma unroll
        for (int i = 0; i < 4; i++)
            #pragma unroll
            for (int j = 0; j < 4; j++)
                k_s[(tx * 4 + j) * 64 + (ty * 4 + i)] = p[i][j];
        __syncthreads();

        // AV: acc[i][c] += sum_j P[r][j] * V[j][c]
        #pragma unroll 16
        for (int j = 0; j < 64; j++) {
            float4 pv = *(const float4*)(k_s + j * 64 + ty * 4);
            float4 vv = *(const float4*)(v_s + j * 64 + tx * 4);
            const float pr[4] = {pv.x, pv.y, pv.z, pv.w};
            const float vc[4] = {vv.x, vv.y, vv.z, vv.w};
            #pragma unroll
            for (int i = 0; i < 4; i++)
                #pragma unroll
                for (int c = 0; c < 4; c++)
                    acc[i][c] = fmaf(pr[i], vc[c], acc[i][c]);
        }
    }

    // epilogue: normalize and write [B,L,H,E] layout (== [8192,1024] row-major)
    #pragma unroll
    for (int i = 0; i < 4; i++) {
        const float inv = 1.0f / l[i];
        const int r = ty * 4 + i;
        float4 o;
        o.x = acc[i][0] * inv; o.y = acc[i][1] * inv;
        o.z = acc[i][2] * inv; o.w = acc[i][3] * inv;
        *(float4*)(go + (size_t)(b * LSEQ + q0 + r) * DMODEL + h * EDIM + tx * 4) = o;
    }
}

// ---------------------------------------------------------------------------
// launch
// ---------------------------------------------------------------------------
extern "C" void kernel_launch(void* const* d_in, const int* in_sizes, int n_in,
                              void* d_out, int out_size)
{
    (void)in_sizes; (void)n_in; (void)out_size;
    const float* queries = (const float*)d_in[0];
    const float* keys    = (const float*)d_in[1];
    const float* values  = (const float*)d_in[2];
    const float* Wq = (const float*)d_in[3];
    const float* bq = (const float*)d_in[4];
    const float* Wk = (const float*)d_in[5];
    const float* bk = (const float*)d_in[6];
    const float* Wv = (const float*)d_in[7];
    const float* bv = (const float*)d_in[8];
    const float* Wo = (const float*)d_in[9];
    const float* bo = (const float*)d_in[10];
    float* out = (float*)d_out;

    float *q, *k, *v, *attn;
    cudaGetSymbolAddress((void**)&q,    g_q);
    cudaGetSymbolAddress((void**)&k,    g_k);
    cudaGetSymbolAddress((void**)&v,    g_v);
    cudaGetSymbolAddress((void**)&attn, g_attn);

    dim3 gemm_grid(GEMM_N / GN, MTOT / GM);   // (8, 64)
    gemm_bias_kernel<<<gemm_grid, 256>>>(queries, Wq, bq, q);
    gemm_bias_kernel<<<gemm_grid, 256>>>(keys,    Wk, bk, k);
    gemm_bias_kernel<<<gemm_grid, 256>>>(values,  Wv, bv, v);

    dim3 attn_grid(LSEQ / 64, BATCH * NHEAD); // (32, 64)
    attn_kernel<<<attn_grid, 256>>>(q, k, v, attn);

    gemm_bias_kernel<<<gemm_grid, 256>>>(attn, Wo, bo, out);
}

// round 3
// speedup vs baseline: 1.3246x; 1.3236x over previous
#include <cuda_runtime.h>
#include <math.h>

#define BATCH 4
#define LSEQ  2048
#define SSEQ  2048
#define DMODEL 1024
#define NHEAD 16
#define EDIM  64
#define MTOT  (BATCH * LSEQ)

typedef unsigned long long ull;

// ---------------------------------------------------------------------------
// f32x2 helpers (SASS FFMA2 path)
// ---------------------------------------------------------------------------
__device__ __forceinline__ ull fma2(ull a, ull b, ull c) {
    ull d; asm("fma.rn.f32x2 %0, %1, %2, %3;" : "=l"(d) : "l"(a), "l"(b), "l"(c));
    return d;
}
__device__ __forceinline__ ull mul2(ull a, ull b) {
    ull d; asm("mul.rn.f32x2 %0, %1, %2;" : "=l"(d) : "l"(a), "l"(b));
    return d;
}
__device__ __forceinline__ ull add2(ull a, ull b) {
    ull d; asm("add.rn.f32x2 %0, %1, %2;" : "=l"(d) : "l"(a), "l"(b));
    return d;
}
__device__ __forceinline__ ull dup2(float x) {
    ull r; asm("mov.b64 %0, {%1, %1};" : "=l"(r) : "f"(x));
    return r;
}
__device__ __forceinline__ ull pk2(float lo, float hi) {
    ull r; asm("mov.b64 %0, {%1, %2};" : "=l"(r) : "f"(lo), "f"(hi));
    return r;
}
__device__ __forceinline__ float2 unpk(ull a) {
    float2 f; asm("mov.b64 {%0, %1}, %2;" : "=f"(f.x), "=f"(f.y) : "l"(a));
    return f;
}

// ---------------------------------------------------------------------------
// Scratch
// ---------------------------------------------------------------------------
__device__ float g_q[MTOT * DMODEL];
__device__ float g_k[MTOT * DMODEL];
__device__ float g_v[MTOT * DMODEL];
__device__ float g_attn[MTOT * DMODEL];

// ---------------------------------------------------------------------------
// SGEMM (f32x2): C[M,N] = A[M,K] @ W[K,N] + bias
// 128x128 tile, BK=16, 256 threads, 8x8 micro as 8x4 f32x2 pairs along N.
// Double-buffered smem with register prefetch.
// ---------------------------------------------------------------------------
#define GM 128
#define GN 128
#define GK 16
#define GEMM_N 1024
#define GEMM_K 1024

__global__ __launch_bounds__(256, 2) void gemm_bias_kernel(
    const float* __restrict__ A, const float* __restrict__ W,
    const float* __restrict__ bias, float* __restrict__ C)
{
    __shared__ float a_s[2][GK][GM + 4];
    __shared__ float w_s[2][GK][GN];

    const int tid = threadIdx.x;
    const int tx = tid & 15;
    const int ty = tid >> 4;
    const int m_base = blockIdx.y * GM;
    const int n_base = blockIdx.x * GN;

    const int arow  = tid >> 2;
    const int acol4 = (tid & 3) * 4;
    const int wrow  = tid >> 5;
    const int wcol4 = (tid & 31) * 4;

    const float* Aptr = A + (size_t)(m_base + arow) * GEMM_K + acol4;
    const float* Wptr = W + (size_t)wrow * GEMM_N + n_base + wcol4;

    ull acc[8][4];
    #pragma unroll
    for (int i = 0; i < 8; i++)
        #pragma unroll
        for (int j = 0; j < 4; j++) acc[i][j] = 0ull;

    // prefetch tile 0
    float4 apre0 = *(const float4*)(Aptr);
    float4 apre1 = *(const float4*)(Aptr + (size_t)64 * GEMM_K);
    float4 wpre0 = *(const float4*)(Wptr);
    float4 wpre1 = *(const float4*)(Wptr + (size_t)8 * GEMM_N);

    a_s[0][acol4 + 0][arow] = apre0.x;
    a_s[0][acol4 + 1][arow] = apre0.y;
    a_s[0][acol4 + 2][arow] = apre0.z;
    a_s[0][acol4 + 3][arow] = apre0.w;
    a_s[0][acol4 + 0][arow + 64] = apre1.x;
    a_s[0][acol4 + 1][arow + 64] = apre1.y;
    a_s[0][acol4 + 2][arow + 64] = apre1.z;
    a_s[0][acol4 + 3][arow + 64] = apre1.w;
    *(float4*)&w_s[0][wrow][wcol4]     = wpre0;
    *(float4*)&w_s[0][wrow + 8][wcol4] = wpre1;
    __syncthreads();

    int buf = 0;
    const int NT = GEMM_K / GK;   // 64
    for (int t = 0; t < NT; t++) {
        if (t < NT - 1) {
            const float* ap = Aptr + (t + 1) * GK;
            apre0 = *(const float4*)ap;
            apre1 = *(const float4*)(ap + (size_t)64 * GEMM_K);
            const float* wp = Wptr + (size_t)(t + 1) * GK * GEMM_N;
            wpre0 = *(const float4*)wp;
            wpre1 = *(const float4*)(wp + (size_t)8 * GEMM_N);
        }
        #pragma unroll
        for (int k = 0; k < GK; k++) {
            float4 a0 = *(const float4*)&a_s[buf][k][ty * 4];
            float4 a1 = *(const float4*)&a_s[buf][k][ty * 4 + 64];
            ulonglong2 b0 = *(const ulonglong2*)&w_s[buf][k][tx * 4];
            ulonglong2 b1 = *(const ulonglong2*)&w_s[buf][k][tx * 4 + 64];
            ull ad[8] = {dup2(a0.x), dup2(a0.y), dup2(a0.z), dup2(a0.w),
                         dup2(a1.x), dup2(a1.y), dup2(a1.z), dup2(a1.w)};
            #pragma unroll
            for (int i = 0; i < 8; i++) {
                acc[i][0] = fma2(ad[i], b0.x, acc[i][0]);
                acc[i][1] = fma2(ad[i], b0.y, acc[i][1]);
                acc[i][2] = fma2(ad[i], b1.x, acc[i][2]);
                acc[i][3] = fma2(ad[i], b1.y, acc[i][3]);
            }
        }
        if (t < NT - 1) {
            const int nb = buf ^ 1;
            a_s[nb][acol4 + 0][arow] = apre0.x;
            a_s[nb][acol4 + 1][arow] = apre0.y;
            a_s[nb][acol4 + 2][arow] = apre0.z;
            a_s[nb][acol4 + 3][arow] = apre0.w;
            a_s[nb][acol4 + 0][arow + 64] = apre1.x;
            a_s[nb][acol4 + 1][arow + 64] = apre1.y;
            a_s[nb][acol4 + 2][arow + 64] = apre1.z;
            a_s[nb][acol4 + 3][arow + 64] = apre1.w;
            *(float4*)&w_s[nb][wrow][wcol4]     = wpre0;
            *(float4*)&w_s[nb][wrow + 8][wcol4] = wpre1;
            __syncthreads();
            buf = nb;
        }
    }

    // epilogue with bias
    float4 blo = *(const float4*)(bias + n_base + tx * 4);
    float4 bhi = *(const float4*)(bias + n_base + tx * 4 + 64);
    #pragma unroll
    for (int i = 0; i < 8; i++) {
        const int m = m_base + ty * 4 + (i & 3) + (i >> 2) * 64;
        float2 p0 = unpk(acc[i][0]);
        float2 p1 = unpk(acc[i][1]);
        float2 p2 = unpk(acc[i][2]);
        float2 p3 = unpk(acc[i][3]);
        float4 lo = make_float4(p0.x + blo.x, p0.y + blo.y, p1.x + blo.z, p1.y + blo.w);
        float4 hi = make_float4(p2.x + bhi.x, p2.y + bhi.y, p3.x + bhi.z, p3.y + bhi.w);
        *(float4*)(C + (size_t)m * GEMM_N + n_base + tx * 4)      = lo;
        *(float4*)(C + (size_t)m * GEMM_N + n_base + tx * 4 + 64) = hi;
    }
}

// ---------------------------------------------------------------------------
// Flash attention (f32x2): 128 query rows x 128 S-tile per CTA, 256 threads.
// QK: pairs along j (dup Q).  AV: pairs along r (dup V), tx split into two
// j-groups; partial accumulators merged by shfl_xor(8) at the epilogue.
// Dynamic smem 169,984 B -> 1 CTA/SM.
// ---------------------------------------------------------------------------
#define TQ 128
#define TS 128
#define QS_OFF 0                    // q_s[e][r]  : [64][132]
#define KS_OFF 8448                 // k_s[e][j]  : [64][132]
#define VS_OFF 16896                // v_s[j][c]  : [128][68]
#define PS_OFF 25600                // p_s[j][r]  : [128][132]
#define ATTN_SMEM_FLOATS 42496
#define ATTN_SMEM_BYTES  (ATTN_SMEM_FLOATS * 4)

__global__ __launch_bounds__(256, 1) void attn_kernel(
    const float* __restrict__ gq, const float* __restrict__ gk,
    const float* __restrict__ gv, float* __restrict__ go)
{
    extern __shared__ float smem[];
    float* q_s = smem + QS_OFF;
    float* k_s = smem + KS_OFF;
    float* v_s = smem + VS_OFF;
    float* p_s = smem + PS_OFF;

    const int bh = blockIdx.y;
    const int b = bh / NHEAD;
    const int h = bh % NHEAD;
    const int q0 = blockIdx.x * TQ;
    const int tid = threadIdx.x;
    const int tx = tid & 15;
    const int ty = tid >> 4;

    const float* qbase = gq + (size_t)b * LSEQ * DMODEL + h * EDIM;
    const float* kbase = gk + (size_t)b * SSEQ * DMODEL + h * EDIM;
    const float* vbase = gv + (size_t)b * SSEQ * DMODEL + h * EDIM;

    const int lr = tid >> 4;      // 0..15 : row within 16-row group
    const int lf = tid & 15;      // float4 index within 64-float row

    // ---- load Q (scaled by 1/sqrt(E)), transposed q_s[e][r] ----
    #pragma unroll
    for (int rr = 0; rr < 8; rr++) {
        const int r = rr * 16 + lr;
        float4 qv = *(const float4*)(qbase + (size_t)(q0 + r) * DMODEL + lf * 4);
        q_s[(lf * 4 + 0) * 132 + r] = qv.x * 0.125f;
        q_s[(lf * 4 + 1) * 132 + r] = qv.y * 0.125f;
        q_s[(lf * 4 + 2) * 132 + r] = qv.z * 0.125f;
        q_s[(lf * 4 + 3) * 132 + r] = qv.w * 0.125f;
    }

    // softmax state: rows ty*4 + {0..3} and ty*4+64+{0..3}
    float m[8], l[8];
    #pragma unroll
    for (int i = 0; i < 8; i++) { m[i] = -1e30f; l[i] = 0.0f; }

    // AV accumulator: 4 row-pairs x 8 cols (this thread's j-group partial)
    ull acc[4][8];
    #pragma unroll
    for (int i = 0; i < 4; i++)
        #pragma unroll
        for (int c = 0; c < 8; c++) acc[i][c] = 0ull;

    const int grp = tx >> 3;            // j-group for AV
    const int cb  = (tx & 7) * 8;       // col base for AV

    for (int s0 = 0; s0 < SSEQ; s0 += TS) {
        __syncthreads();
        // ---- load K (transposed k_s[e][j]) and V (natural v_s[j][c]) ----
        #pragma unroll
        for (int rr = 0; rr < 8; rr++) {
            const int j = rr * 16 + lr;
            float4 kv = *(const float4*)(kbase + (size_t)(s0 + j) * DMODEL + lf * 4);
            k_s[(lf * 4 + 0) * 132 + j] = kv.x;
            k_s[(lf * 4 + 1) * 132 + j] = kv.y;
            k_s[(lf * 4 + 2) * 132 + j] = kv.z;
            k_s[(lf * 4 + 3) * 132 + j] = kv.w;
            float4 vv = *(const float4*)(vbase + (size_t)(s0 + j) * DMODEL + lf * 4);
            *(float4*)&v_s[j * 68 + lf * 4] = vv;
        }
        __syncthreads();

        // ---- QK^T: sc[i][jp], pairs along j ----
        ull sc[8][4];
        #pragma unroll
        for (int i = 0; i < 8; i++)
            #pragma unroll
            for (int jp = 0; jp < 4; jp++) sc[i][jp] = 0ull;

        #pragma unroll 4
        for (int e = 0; e < EDIM; e++) {
            float4 qa = *(const float4*)&q_s[e * 132 + ty * 4];
            float4 qb = *(const float4*)&q_s[e * 132 + ty * 4 + 64];
            ulonglong2 k0 = *(const ulonglong2*)&k_s[e * 132 + tx * 4];
            ulonglong2 k1 = *(const ulonglong2*)&k_s[e * 132 + tx * 4 + 64];
            ull qd[8] = {dup2(qa.x), dup2(qa.y), dup2(qa.z), dup2(qa.w),
                         dup2(qb.x), dup2(qb.y), dup2(qb.z), dup2(qb.w)};
            #pragma unroll
            for (int i = 0; i < 8; i++) {
                sc[i][0] = fma2(qd[i], k0.x, sc[i][0]);
                sc[i][1] = fma2(qd[i], k0.y, sc[i][1]);
                sc[i][2] = fma2(qd[i], k1.x, sc[i][2]);
                sc[i][3] = fma2(qd[i], k1.y, sc[i][3]);
            }
        }

        // ---- online softmax (per-row; all 16 tx lanes redundant) ----
        float p[8][8];
        float corr[8];
        #pragma unroll
        for (int i = 0; i < 8; i++) {
            float2 s0v = unpk(sc[i][0]);
            float2 s1v = unpk(sc[i][1]);
            float2 s2v = unpk(sc[i][2]);
            float2 s3v = unpk(sc[i][3]);
            float sv[8] = {s0v.x, s0v.y, s1v.x, s1v.y, s2v.x, s2v.y, s3v.x, s3v.y};
            float tm = sv[0];
            #pragma unroll
            for (int j = 1; j < 8; j++) tm = fmaxf(tm, sv[j]);
            #pragma unroll
            for (int off = 1; off < 16; off <<= 1)
                tm = fmaxf(tm, __shfl_xor_sync(0xffffffffu, tm, off));
            const float newm = fmaxf(m[i], tm);
            corr[i] = __expf(m[i] - newm);
            m[i] = newm;
            float rs = 0.0f;
            #pragma unroll
            for (int j = 0; j < 8; j++) {
                p[i][j] = __expf(sv[j] - newm);
                rs += p[i][j];
            }
            #pragma unroll
            for (int off = 1; off < 16; off <<= 1)
                rs += __shfl_xor_sync(0xffffffffu, rs, off);
            l[i] = l[i] * corr[i] + rs;
        }

        // rescale accumulators (pairs along r)
        #pragma unroll
        for (int rp = 0; rp < 4; rp++) {
            ull c2 = pk2(corr[2 * rp], corr[2 * rp + 1]);
            #pragma unroll
            for (int c = 0; c < 8; c++) acc[rp][c] = mul2(acc[rp][c], c2);
        }

        // ---- store P transposed: p_s[j][r] ----
        #pragma unroll
        for (int jj = 0; jj < 8; jj++) {
            const int j = tx * 4 + (jj & 3) + (jj >> 2) * 64;
            float4 lo = make_float4(p[0][jj], p[1][jj], p[2][jj], p[3][jj]);
            float4 hi = make_float4(p[4][jj], p[5][jj], p[6][jj], p[7][jj]);
            *(float4*)&p_s[j * 132 + ty * 4]      = lo;
            *(float4*)&p_s[j * 132 + ty * 4 + 64] = hi;
        }
        __syncthreads();

        // ---- AV: acc[rp][c] += P-pair(r) * dup(V[j][c]), this group's 64 j ----
        #pragma unroll 4
        for (int jj = 0; jj < 64; jj++) {
            const int j = grp * 64 + jj;
            ulonglong2 pa = *(const ulonglong2*)&p_s[j * 132 + ty * 4];
            ulonglong2 pb = *(const ulonglong2*)&p_s[j * 132 + ty * 4 + 64];
            float4 va = *(const float4*)&v_s[j * 68 + cb];
            float4 vb = *(const float4*)&v_s[j * 68 + cb + 4];
            ull vd[8] = {dup2(va.x), dup2(va.y), dup2(va.z), dup2(va.w),
                         dup2(vb.x), dup2(vb.y), dup2(vb.z), dup2(vb.w)};
            #pragma unroll
            for (int c = 0; c < 8; c++) {
                acc[0][c] = fma2(pa.x, vd[c], acc[0][c]);
                acc[1][c] = fma2(pa.y, vd[c], acc[1][c]);
                acc[2][c] = fma2(pb.x, vd[c], acc[2][c]);
                acc[3][c] = fma2(pb.y, vd[c], acc[3][c]);
            }
        }
    }

    // ---- epilogue: normalize, merge j-groups (shfl xor 8), write ----
    #pragma unroll
    for (int rp = 0; rp < 4; rp++) {
        ull inv2 = pk2(1.0f / l[2 * rp], 1.0f / l[2 * rp + 1]);
        #pragma unroll
        for (int c = 0; c < 8; c++) {
            ull v = mul2(acc[rp][c], inv2);
            ull o = __shfl_xor_sync(0xffffffffu, v, 8);
            acc[rp][c] = add2(v, o);
        }
    }
    if ((tx & 8) == 0) {
        #pragma unroll
        for (int rp = 0; rp < 4; rp++) {
            const int rowbase = ty * 4 + (rp >> 1) * 64 + (rp & 1) * 2;
            float2 u[8];
            #pragma unroll
            for (int c = 0; c < 8; c++) u[c] = unpk(acc[rp][c]);
            float* out0 = go + (size_t)(b * LSEQ + q0 + rowbase) * DMODEL + h * EDIM + cb;
            float* out1 = go + (size_t)(b * LSEQ + q0 + rowbase + 1) * DMODEL + h * EDIM + cb;
            *(float4*)(out0)     = make_float4(u[0].x, u[1].x, u[2].x, u[3].x);
            *(float4*)(out0 + 4) = make_float4(u[4].x, u[5].x, u[6].x, u[7].x);
            *(float4*)(out1)     = make_float4(u[0].y, u[1].y, u[2].y, u[3].y);
            *(float4*)(out1 + 4) = make_float4(u[4].y, u[5].y, u[6].y, u[7].y);
        }
    }
}

// ---------------------------------------------------------------------------
// launch
// ---------------------------------------------------------------------------
extern "C" void kernel_launch(void* const* d_in, const int* in_sizes, int n_in,
                              void* d_out, int out_size)
{
    (void)in_sizes; (void)n_in; (void)out_size;
    const float* queries = (const float*)d_in[0];
    const float* keys    = (const float*)d_in[1];
    const float* values  = (const float*)d_in[2];
    const float* Wq = (const float*)d_in[3];
    const float* bq = (const float*)d_in[4];
    const float* Wk = (const float*)d_in[5];
    const float* bk = (const float*)d_in[6];
    const float* Wv = (const float*)d_in[7];
    const float* bv = (const float*)d_in[8];
    const float* Wo = (const float*)d_in[9];
    const float* bo = (const float*)d_in[10];
    float* out = (float*)d_out;

    float *q, *k, *v, *attn;
    cudaGetSymbolAddress((void**)&q,    g_q);
    cudaGetSymbolAddress((void**)&k,    g_k);
    cudaGetSymbolAddress((void**)&v,    g_v);
    cudaGetSymbolAddress((void**)&attn, g_attn);

    cudaFuncSetAttribute(attn_kernel,
                         cudaFuncAttributeMaxDynamicSharedMemorySize,
                         ATTN_SMEM_BYTES);

    dim3 gemm_grid(GEMM_N / GN, MTOT / GM);   // (8, 64)
    gemm_bias_kernel<<<gemm_grid, 256>>>(queries, Wq, bq, q);
    gemm_bias_kernel<<<gemm_grid, 256>>>(keys,    Wk, bk, k);
    gemm_bias_kernel<<<gemm_grid, 256>>>(values,  Wv, bv, v);

    dim3 attn_grid(LSEQ / TQ, BATCH * NHEAD); // (16, 64)
    attn_kernel<<<attn_grid, 256, ATTN_SMEM_BYTES>>>(q, k, v, attn);

    gemm_bias_kernel<<<gemm_grid, 256>>>(attn, Wo, bo, out);
}

// round 6
// speedup vs baseline: 1.8028x; 1.3610x over previous
#include <cuda_runtime.h>
#include <math.h>
#include <stdint.h>

// R6 = R5 resubmission (R5 bench was an infra failure: "GB300 container
// failed twice" — kernel never compiled/ran). tf32 mma.sync GEMMs + FFMA2
// flash attention.

#define BATCH 4
#define LSEQ  2048
#define SSEQ  2048
#define DMODEL 1024
#define NHEAD 16
#define EDIM  64
#define MTOT  (BATCH * LSEQ)

typedef unsigned long long ull;

// ---------------------------------------------------------------------------
// f32x2 helpers (FFMA2) — attention kernel
// ---------------------------------------------------------------------------
__device__ __forceinline__ ull fma2(ull a, ull b, ull c) {
    ull d; asm("fma.rn.f32x2 %0, %1, %2, %3;" : "=l"(d) : "l"(a), "l"(b), "l"(c));
    return d;
}
__device__ __forceinline__ ull mul2(ull a, ull b) {
    ull d; asm("mul.rn.f32x2 %0, %1, %2;" : "=l"(d) : "l"(a), "l"(b));
    return d;
}
__device__ __forceinline__ ull add2(ull a, ull b) {
    ull d; asm("add.rn.f32x2 %0, %1, %2;" : "=l"(d) : "l"(a), "l"(b));
    return d;
}
__device__ __forceinline__ ull dup2(float x) {
    ull r; asm("mov.b64 %0, {%1, %1};" : "=l"(r) : "f"(x));
    return r;
}
__device__ __forceinline__ ull pk2(float lo, float hi) {
    ull r; asm("mov.b64 %0, {%1, %2};" : "=l"(r) : "f"(lo), "f"(hi));
    return r;
}
__device__ __forceinline__ float2 unpk(ull a) {
    float2 f; asm("mov.b64 {%0, %1}, %2;" : "=f"(f.x), "=f"(f.y) : "l"(a));
    return f;
}

// ---------------------------------------------------------------------------
// tf32 mma.sync helpers (legacy HMMA path — works on compute_100)
// ---------------------------------------------------------------------------
__device__ __forceinline__ uint32_t f2tf(float f) {
    uint32_t r; asm("cvt.rna.tf32.f32 %0, %1;" : "=r"(r) : "f"(f));
    return r;
}
__device__ __forceinline__ void mma_tf32(float d[4], const uint32_t a[4],
                                         uint32_t b0, uint32_t b1) {
    asm volatile(
        "mma.sync.aligned.m16n8k8.row.col.f32.tf32.tf32.f32 "
        "{%0,%1,%2,%3}, {%4,%5,%6,%7}, {%8,%9}, {%0,%1,%2,%3};"
        : "+f"(d[0]), "+f"(d[1]), "+f"(d[2]), "+f"(d[3])
        : "r"(a[0]), "r"(a[1]), "r"(a[2]), "r"(a[3]), "r"(b0), "r"(b1));
}

// ---------------------------------------------------------------------------
// Scratch
// ---------------------------------------------------------------------------
__device__ float g_q[MTOT * DMODEL];
__device__ float g_k[MTOT * DMODEL];
__device__ float g_v[MTOT * DMODEL];
__device__ float g_attn[MTOT * DMODEL];

// ---------------------------------------------------------------------------
// tf32 mma.sync GEMM: C[8192,1024] = A[8192,1024] @ W[1024,1024] + bias
// 128x128 tile, BK=16, 256 thr (8 warps x 32x64), double-buffered.
// A smem [m][k] stride 20 words; B smem [k][n] stride 136 words.
// Elements stored pre-converted to tf32 (cvt at STS time).
// ---------------------------------------------------------------------------
#define GEMM_N 1024
#define GEMM_K 1024
#define BK 16
#define ASTR 20
#define BSTR 136

__global__ __launch_bounds__(256, 2) void gemm_tf32_kernel(
    const float* __restrict__ A, const float* __restrict__ W,
    const float* __restrict__ bias, float* __restrict__ C)
{
    __shared__ uint32_t a_s[2][128 * ASTR];   // 20480 B
    __shared__ uint32_t b_s[2][BK * BSTR];    // 17408 B

    const int tid = threadIdx.x;
    const int wid = tid >> 5;
    const int lane = tid & 31;
    const int gidr = lane >> 2;          // 0..7
    const int tig  = lane & 3;           // 0..3
    const int m_base = blockIdx.y * 128;
    const int n_base = blockIdx.x * 128;
    const int warp_m = (wid & 3) * 32;
    const int warp_n = (wid >> 2) * 64;

    // global-load mappings
    const int ar0 = tid >> 2;            // A row
    const int aq  = tid & 3;             // A col-quad
    const int br0 = tid >> 5;            // B k-row
    const int bq  = tid & 31;            // B col-quad

    float acc[2][8][4];
    #pragma unroll
    for (int ma = 0; ma < 2; ma++)
        #pragma unroll
        for (int na = 0; na < 8; na++)
            #pragma unroll
            for (int f = 0; f < 4; f++) acc[ma][na][f] = 0.0f;

    float4 av[2], bv[2];

    #define LDG_STAGE(t)                                                          \
        do {                                                                      \
            const int k0_ = (t) * BK;                                             \
            av[0] = *(const float4*)(A + (size_t)(m_base + ar0) * GEMM_K + k0_ + aq * 4);       \
            av[1] = *(const float4*)(A + (size_t)(m_base + ar0 + 64) * GEMM_K + k0_ + aq * 4);  \
            bv[0] = *(const float4*)(W + (size_t)(k0_ + br0) * GEMM_N + n_base + bq * 4);       \
            bv[1] = *(const float4*)(W + (size_t)(k0_ + br0 + 8) * GEMM_N + n_base + bq * 4);   \
        } while (0)

    #define STS_STAGE(bf)                                                         \
        do {                                                                      \
            uint32_t* ap0 = &a_s[bf][ar0 * ASTR + aq * 4];                        \
            ap0[0] = f2tf(av[0].x); ap0[1] = f2tf(av[0].y);                       \
            ap0[2] = f2tf(av[0].z); ap0[3] = f2tf(av[0].w);                       \
            uint32_t* ap1 = &a_s[bf][(ar0 + 64) * ASTR + aq * 4];                 \
            ap1[0] = f2tf(av[1].x); ap1[1] = f2tf(av[1].y);                       \
            ap1[2] = f2tf(av[1].z); ap1[3] = f2tf(av[1].w);                       \
            uint4 bw0 = make_uint4(f2tf(bv[0].x), f2tf(bv[0].y),                  \
                                   f2tf(bv[0].z), f2tf(bv[0].w));                 \
            uint4 bw1 = make_uint4(f2tf(bv[1].x), f2tf(bv[1].y),                  \
                                   f2tf(bv[1].z), f2tf(bv[1].w));                 \
            *(uint4*)&b_s[bf][br0 * BSTR + bq * 4]       = bw0;                   \
            *(uint4*)&b_s[bf][(br0 + 8) * BSTR + bq * 4] = bw1;                   \
        } while (0)

    LDG_STAGE(0);
    STS_STAGE(0);
    __syncthreads();

    const int NSTAGE = GEMM_K / BK;   // 64
    for (int t = 0; t < NSTAGE; t++) {
        const int buf = t & 1;
        if (t < NSTAGE - 1) LDG_STAGE(t + 1);

        #pragma unroll
        for (int kk = 0; kk < 2; kk++) {
            const int kb = kk * 8;
            uint32_t af[2][4];
            #pragma unroll
            for (int ma = 0; ma < 2; ma++) {
                const uint32_t* ap =
                    &a_s[buf][(warp_m + ma * 16 + gidr) * ASTR + kb + tig];
                af[ma][0] = ap[0];
                af[ma][1] = ap[8 * ASTR];
                af[ma][2] = ap[4];
                af[ma][3] = ap[8 * ASTR + 4];
            }
            #pragma unroll
            for (int na = 0; na < 8; na++) {
                const uint32_t* bp =
                    &b_s[buf][(kb + tig) * BSTR + warp_n + na * 8 + gidr];
                const uint32_t b0 = bp[0];
                const uint32_t b1 = bp[4 * BSTR];
                mma_tf32(acc[0][na], af[0], b0, b1);
                mma_tf32(acc[1][na], af[1], b0, b1);
            }
        }

        if (t < NSTAGE - 1) {
            STS_STAGE((t + 1) & 1);
            __syncthreads();
        }
    }

    // epilogue + bias
    #pragma unroll
    for (int na = 0; na < 8; na++) {
        const int col = n_base + warp_n + na * 8 + tig * 2;
        const float bx = __ldg(bias + col);
        const float by = __ldg(bias + col + 1);
        #pragma unroll
        for (int ma = 0; ma < 2; ma++) {
            const int r0 = m_base + warp_m + ma * 16 + gidr;
            float2 lo = make_float2(acc[ma][na][0] + bx, acc[ma][na][1] + by);
            float2 hi = make_float2(acc[ma][na][2] + bx, acc[ma][na][3] + by);
            *(float2*)(C + (size_t)r0 * GEMM_N + col)       = lo;
            *(float2*)(C + (size_t)(r0 + 8) * GEMM_N + col) = hi;
        }
    }
}

// ---------------------------------------------------------------------------
// Flash attention (f32x2): unchanged from R3 (proven 1.72 ms)
// ---------------------------------------------------------------------------
#define TQ 128
#define TS 128
#define QS_OFF 0
#define KS_OFF 8448
#define VS_OFF 16896
#define PS_OFF 25600
#define ATTN_SMEM_FLOATS 42496
#define ATTN_SMEM_BYTES  (ATTN_SMEM_FLOATS * 4)

__global__ __launch_bounds__(256, 1) void attn_kernel(
    const float* __restrict__ gq, const float* __restrict__ gk,
    const float* __restrict__ gv, float* __restrict__ go)
{
    extern __shared__ float smem[];
    float* q_s = smem + QS_OFF;
    float* k_s = smem + KS_OFF;
    float* v_s = smem + VS_OFF;
    float* p_s = smem + PS_OFF;

    const int bh = blockIdx.y;
    const int b = bh / NHEAD;
    const int h = bh % NHEAD;
    const int q0 = blockIdx.x * TQ;
    const int tid = threadIdx.x;
    const int tx = tid & 15;
    const int ty = tid >> 4;

    const float* qbase = gq + (size_t)b * LSEQ * DMODEL + h * EDIM;
    const float* kbase = gk + (size_t)b * SSEQ * DMODEL + h * EDIM;
    const float* vbase = gv + (size_t)b * SSEQ * DMODEL + h * EDIM;

    const int lr = tid >> 4;
    const int lf = tid & 15;

    #pragma unroll
    for (int rr = 0; rr < 8; rr++) {
        const int r = rr * 16 + lr;
        float4 qv = *(const float4*)(qbase + (size_t)(q0 + r) * DMODEL + lf * 4);
        q_s[(lf * 4 + 0) * 132 + r] = qv.x * 0.125f;
        q_s[(lf * 4 + 1) * 132 + r] = qv.y * 0.125f;
        q_s[(lf * 4 + 2) * 132 + r] = qv.z * 0.125f;
        q_s[(lf * 4 + 3) * 132 + r] = qv.w * 0.125f;
    }

    float m[8], l[8];
    #pragma unroll
    for (int i = 0; i < 8; i++) { m[i] = -1e30f; l[i] = 0.0f; }

    ull acc[4][8];
    #pragma unroll
    for (int i = 0; i < 4; i++)
        #pragma unroll
        for (int c = 0; c < 8; c++) acc[i][c] = 0ull;

    const int grp = tx >> 3;
    const int cb  = (tx & 7) * 8;

    for (int s0 = 0; s0 < SSEQ; s0 += TS) {
        __syncthreads();
        #pragma unroll
        for (int rr = 0; rr < 8; rr++) {
            const int j = rr * 16 + lr;
            float4 kv = *(const float4*)(kbase + (size_t)(s0 + j) * DMODEL + lf * 4);
            k_s[(lf * 4 + 0) * 132 + j] = kv.x;
            k_s[(lf * 4 + 1) * 132 + j] = kv.y;
            k_s[(lf * 4 + 2) * 132 + j] = kv.z;
            k_s[(lf * 4 + 3) * 132 + j] = kv.w;
            float4 vv = *(const float4*)(vbase + (size_t)(s0 + j) * DMODEL + lf * 4);
            *(float4*)&v_s[j * 68 + lf * 4] = vv;
        }
        __syncthreads();

        ull sc[8][4];
        #pragma unroll
        for (int i = 0; i < 8; i++)
            #pragma unroll
            for (int jp = 0; jp < 4; jp++) sc[i][jp] = 0ull;

        #pragma unroll 4
        for (int e = 0; e < EDIM; e++) {
            float4 qa = *(const float4*)&q_s[e * 132 + ty * 4];
            float4 qb = *(const float4*)&q_s[e * 132 + ty * 4 + 64];
            ulonglong2 k0 = *(const ulonglong2*)&k_s[e * 132 + tx * 4];
            ulonglong2 k1 = *(const ulonglong2*)&k_s[e * 132 + tx * 4 + 64];
            ull qd[8] = {dup2(qa.x), dup2(qa.y), dup2(qa.z), dup2(qa.w),
                         dup2(qb.x), dup2(qb.y), dup2(qb.z), dup2(qb.w)};
            #pragma unroll
            for (int i = 0; i < 8; i++) {
                sc[i][0] = fma2(qd[i], k0.x, sc[i][0]);
                sc[i][1] = fma2(qd[i], k0.y, sc[i][1]);
                sc[i][2] = fma2(qd[i], k1.x, sc[i][2]);
                sc[i][3] = fma2(qd[i], k1.y, sc[i][3]);
            }
        }

        float p[8][8];
        float corr[8];
        #pragma unroll
        for (int i = 0; i < 8; i++) {
            float2 s0v = unpk(sc[i][0]);
            float2 s1v = unpk(sc[i][1]);
            float2 s2v = unpk(sc[i][2]);
            float2 s3v = unpk(sc[i][3]);
            float sv[8] = {s0v.x, s0v.y, s1v.x, s1v.y, s2v.x, s2v.y, s3v.x, s3v.y};
            float tm = sv[0];
            #pragma unroll
            for (int j = 1; j < 8; j++) tm = fmaxf(tm, sv[j]);
            #pragma unroll
            for (int off = 1; off < 16; off <<= 1)
                tm = fmaxf(tm, __shfl_xor_sync(0xffffffffu, tm, off));
            const float newm = fmaxf(m[i], tm);
            corr[i] = __expf(m[i] - newm);
            m[i] = newm;
            float rs = 0.0f;
            #pragma unroll
            for (int j = 0; j < 8; j++) {
                p[i][j] = __expf(sv[j] - newm);
                rs += p[i][j];
            }
            #pragma unroll
            for (int off = 1; off < 16; off <<= 1)
                rs += __shfl_xor_sync(0xffffffffu, rs, off);
            l[i] = l[i] * corr[i] + rs;
        }

        #pragma unroll
        for (int rp = 0; rp < 4; rp++) {
            ull c2 = pk2(corr[2 * rp], corr[2 * rp + 1]);
            #pragma unroll
            for (int c = 0; c < 8; c++) acc[rp][c] = mul2(acc[rp][c], c2);
        }

        #pragma unroll
        for (int jj = 0; jj < 8; jj++) {
            const int j = tx * 4 + (jj & 3) + (jj >> 2) * 64;
            float4 lo = make_float4(p[0][jj], p[1][jj], p[2][jj], p[3][jj]);
            float4 hi = make_float4(p[4][jj], p[5][jj], p[6][jj], p[7][jj]);
            *(float4*)&p_s[j * 132 + ty * 4]      = lo;
            *(float4*)&p_s[j * 132 + ty * 4 + 64] = hi;
        }
        __syncthreads();

        #pragma unroll 4
        for (int jj = 0; jj < 64; jj++) {
            const int j = grp * 64 + jj;
            ulonglong2 pa = *(const ulonglong2*)&p_s[j * 132 + ty * 4];
            ulonglong2 pb = *(const ulonglong2*)&p_s[j * 132 + ty * 4 + 64];
            float4 va = *(const float4*)&v_s[j * 68 + cb];
            float4 vb = *(const float4*)&v_s[j * 68 + cb + 4];
            ull vd[8] = {dup2(va.x), dup2(va.y), dup2(va.z), dup2(va.w),
                         dup2(vb.x), dup2(vb.y), dup2(vb.z), dup2(vb.w)};
            #pragma unroll
            for (int c = 0; c < 8; c++) {
                acc[0][c] = fma2(pa.x, vd[c], acc[0][c]);
                acc[1][c] = fma2(pa.y, vd[c], acc[1][c]);
                acc[2][c] = fma2(pb.x, vd[c], acc[2][c]);
                acc[3][c] = fma2(pb.y, vd[c], acc[3][c]);
            }
        }
    }

    #pragma unroll
    for (int rp = 0; rp < 4; rp++) {
        ull inv2 = pk2(1.0f / l[2 * rp], 1.0f / l[2 * rp + 1]);
        #pragma unroll
        for (int c = 0; c < 8; c++) {
            ull v = mul2(acc[rp][c], inv2);
            ull o = __shfl_xor_sync(0xffffffffu, v, 8);
            acc[rp][c] = add2(v, o);
        }
    }
    if ((tx & 8) == 0) {
        #pragma unroll
        for (int rp = 0; rp < 4; rp++) {
            const int rowbase = ty * 4 + (rp >> 1) * 64 + (rp & 1) * 2;
            float2 u[8];
            #pragma unroll
            for (int c = 0; c < 8; c++) u[c] = unpk(acc[rp][c]);
            float* out0 = go + (size_t)(b * LSEQ + q0 + rowbase) * DMODEL + h * EDIM + cb;
            float* out1 = go + (size_t)(b * LSEQ + q0 + rowbase + 1) * DMODEL + h * EDIM + cb;
            *(float4*)(out0)     = make_float4(u[0].x, u[1].x, u[2].x, u[3].x);
            *(float4*)(out0 + 4) = make_float4(u[4].x, u[5].x, u[6].x, u[7].x);
            *(float4*)(out1)     = make_float4(u[0].y, u[1].y, u[2].y, u[3].y);
            *(float4*)(out1 + 4) = make_float4(u[4].y, u[5].y, u[6].y, u[7].y);
        }
    }
}

// ---------------------------------------------------------------------------
// launch
// ---------------------------------------------------------------------------
extern "C" void kernel_launch(void* const* d_in, const int* in_sizes, int n_in,
                              void* d_out, int out_size)
{
    (void)in_sizes; (void)n_in; (void)out_size;
    const float* queries = (const float*)d_in[0];
    const float* keys    = (const float*)d_in[1];
    const float* values  = (const float*)d_in[2];
    const float* Wq = (const float*)d_in[3];
    const float* bq = (const float*)d_in[4];
    const float* Wk = (const float*)d_in[5];
    const float* bk = (const float*)d_in[6];
    const float* Wv = (const float*)d_in[7];
    const float* bv = (const float*)d_in[8];
    const float* Wo = (const float*)d_in[9];
    const float* bo = (const float*)d_in[10];
    float* out = (float*)d_out;

    float *q, *k, *v, *attn;
    cudaGetSymbolAddress((void**)&q,    g_q);
    cudaGetSymbolAddress((void**)&k,    g_k);
    cudaGetSymbolAddress((void**)&v,    g_v);
    cudaGetSymbolAddress((void**)&attn, g_attn);

    cudaFuncSetAttribute(attn_kernel,
                         cudaFuncAttributeMaxDynamicSharedMemorySize,
                         ATTN_SMEM_BYTES);

    dim3 gemm_grid(GEMM_N / 128, MTOT / 128);   // (8, 64)
    gemm_tf32_kernel<<<gemm_grid, 256>>>(queries, Wq, bq, q);
    gemm_tf32_kernel<<<gemm_grid, 256>>>(keys,    Wk, bk, k);
    gemm_tf32_kernel<<<gemm_grid, 256>>>(values,  Wv, bv, v);

    dim3 attn_grid(LSEQ / TQ, BATCH * NHEAD);   // (16, 64)
    attn_kernel<<<attn_grid, 256, ATTN_SMEM_BYTES>>>(q, k, v, attn);

    gemm_tf32_kernel<<<gemm_grid, 256>>>(attn, Wo, bo, out);
}

// round 7
// speedup vs baseline: 2.0697x; 1.1481x over previous
#include <cuda_runtime.h>
#include <math.h>
#include <stdint.h>

// R7: tf32 mma.sync for BOTH the projections (R6, proven) and flash attention.

#define BATCH 4
#define LSEQ  2048
#define SSEQ  2048
#define DMODEL 1024
#define NHEAD 16
#define EDIM  64
#define MTOT  (BATCH * LSEQ)

// ---------------------------------------------------------------------------
// tf32 mma.sync helpers
// ---------------------------------------------------------------------------
__device__ __forceinline__ uint32_t f2tf(float f) {
    uint32_t r; asm("cvt.rna.tf32.f32 %0, %1;" : "=r"(r) : "f"(f));
    return r;
}
__device__ __forceinline__ void mma_tf32(float d[4], uint32_t a0, uint32_t a1,
                                         uint32_t a2, uint32_t a3,
                                         uint32_t b0, uint32_t b1) {
    asm volatile(
        "mma.sync.aligned.m16n8k8.row.col.f32.tf32.tf32.f32 "
        "{%0,%1,%2,%3}, {%4,%5,%6,%7}, {%8,%9}, {%0,%1,%2,%3};"
        : "+f"(d[0]), "+f"(d[1]), "+f"(d[2]), "+f"(d[3])
        : "r"(a0), "r"(a1), "r"(a2), "r"(a3), "r"(b0), "r"(b1));
}

// ---------------------------------------------------------------------------
// Scratch
// ---------------------------------------------------------------------------
__device__ float g_q[MTOT * DMODEL];
__device__ float g_k[MTOT * DMODEL];
__device__ float g_v[MTOT * DMODEL];
__device__ float g_attn[MTOT * DMODEL];

// ---------------------------------------------------------------------------
// tf32 mma.sync GEMM (unchanged from R6 — proven 144 us/GEMM)
// ---------------------------------------------------------------------------
#define GEMM_N 1024
#define GEMM_K 1024
#define BK 16
#define ASTR 20
#define BSTR 136

__global__ __launch_bounds__(256, 2) void gemm_tf32_kernel(
    const float* __restrict__ A, const float* __restrict__ W,
    const float* __restrict__ bias, float* __restrict__ C)
{
    __shared__ uint32_t a_s[2][128 * ASTR];
    __shared__ uint32_t b_s[2][BK * BSTR];

    const int tid = threadIdx.x;
    const int wid = tid >> 5;
    const int lane = tid & 31;
    const int gidr = lane >> 2;
    const int tig  = lane & 3;
    const int m_base = blockIdx.y * 128;
    const int n_base = blockIdx.x * 128;
    const int warp_m = (wid & 3) * 32;
    const int warp_n = (wid >> 2) * 64;

    const int ar0 = tid >> 2;
    const int aq  = tid & 3;
    const int br0 = tid >> 5;
    const int bq  = tid & 31;

    float acc[2][8][4];
    #pragma unroll
    for (int ma = 0; ma < 2; ma++)
        #pragma unroll
        for (int na = 0; na < 8; na++)
            #pragma unroll
            for (int f = 0; f < 4; f++) acc[ma][na][f] = 0.0f;

    float4 av[2], bv[2];

    #define LDG_STAGE(t)                                                          \
        do {                                                                      \
            const int k0_ = (t) * BK;                                             \
            av[0] = *(const float4*)(A + (size_t)(m_base + ar0) * GEMM_K + k0_ + aq * 4);       \
            av[1] = *(const float4*)(A + (size_t)(m_base + ar0 + 64) * GEMM_K + k0_ + aq * 4);  \
            bv[0] = *(const float4*)(W + (size_t)(k0_ + br0) * GEMM_N + n_base + bq * 4);       \
            bv[1] = *(const float4*)(W + (size_t)(k0_ + br0 + 8) * GEMM_N + n_base + bq * 4);   \
        } while (0)

    #define STS_STAGE(bf)                                                         \
        do {                                                                      \
            uint32_t* ap0 = &a_s[bf][ar0 * ASTR + aq * 4];                        \
            ap0[0] = f2tf(av[0].x); ap0[1] = f2tf(av[0].y);                       \
            ap0[2] = f2tf(av[0].z); ap0[3] = f2tf(av[0].w);                       \
            uint32_t* ap1 = &a_s[bf][(ar0 + 64) * ASTR + aq * 4];                 \
            ap1[0] = f2tf(av[1].x); ap1[1] = f2tf(av[1].y);                       \
            ap1[2] = f2tf(av[1].z); ap1[3] = f2tf(av[1].w);                       \
            uint4 bw0 = make_uint4(f2tf(bv[0].x), f2tf(bv[0].y),                  \
                                   f2tf(bv[0].z), f2tf(bv[0].w));                 \
            uint4 bw1 = make_uint4(f2tf(bv[1].x), f2tf(bv[1].y),                  \
                                   f2tf(bv[1].z), f2tf(bv[1].w));                 \
            *(uint4*)&b_s[bf][br0 * BSTR + bq * 4]       = bw0;                   \
            *(uint4*)&b_s[bf][(br0 + 8) * BSTR + bq * 4] = bw1;                   \
        } while (0)

    LDG_STAGE(0);
    STS_STAGE(0);
    __syncthreads();

    const int NSTAGE = GEMM_K / BK;
    for (int t = 0; t < NSTAGE; t++) {
        const int buf = t & 1;
        if (t < NSTAGE - 1) LDG_STAGE(t + 1);

        #pragma unroll
        for (int kk = 0; kk < 2; kk++) {
            const int kb = kk * 8;
            uint32_t af[2][4];
            #pragma unroll
            for (int ma = 0; ma < 2; ma++) {
                const uint32_t* ap =
                    &a_s[buf][(warp_m + ma * 16 + gidr) * ASTR + kb + tig];
                af[ma][0] = ap[0];
                af[ma][1] = ap[8 * ASTR];
                af[ma][2] = ap[4];
                af[ma][3] = ap[8 * ASTR + 4];
            }
            #pragma unroll
            for (int na = 0; na < 8; na++) {
                const uint32_t* bp =
                    &b_s[buf][(kb + tig) * BSTR + warp_n + na * 8 + gidr];
                const uint32_t b0 = bp[0];
                const uint32_t b1 = bp[4 * BSTR];
                mma_tf32(acc[0][na], af[0][0], af[0][1], af[0][2], af[0][3], b0, b1);
                mma_tf32(acc[1][na], af[1][0], af[1][1], af[1][2], af[1][3], b0, b1);
            }
        }

        if (t < NSTAGE - 1) {
            STS_STAGE((t + 1) & 1);
            __syncthreads();
        }
    }

    #pragma unroll
    for (int na = 0; na < 8; na++) {
        const int col = n_base + warp_n + na * 8 + tig * 2;
        const float bx = __ldg(bias + col);
        const float by = __ldg(bias + col + 1);
        #pragma unroll
        for (int ma = 0; ma < 2; ma++) {
            const int r0 = m_base + warp_m + ma * 16 + gidr;
            float2 lo = make_float2(acc[ma][na][0] + bx, acc[ma][na][1] + by);
            float2 hi = make_float2(acc[ma][na][2] + bx, acc[ma][na][3] + by);
            *(float2*)(C + (size_t)r0 * GEMM_N + col)       = lo;
            *(float2*)(C + (size_t)(r0 + 8) * GEMM_N + col) = hi;
        }
    }
}

// ---------------------------------------------------------------------------
// Flash attention via tf32 mma.sync.
// CTA: 128 q-rows x 128 S-tile, 8 warps (warp w: q rows w*16..w*16+15).
// Smem layouts (tf32 words, mod-4 permuted for contiguous fragment LDS):
//   p_s [q:128][perm j: (j&3)*32 + (j>>2)] stride 132   (also Q staging)
//   k_s [s:128][perm e: (e&3)*16 + (e>>2)] stride 68
//   v_s [c: 64][perm j: (j&3)*32 + (j>>2)] stride 132   (transposed V)
// ---------------------------------------------------------------------------
#define PSTR 132
#define KSTR 68
#define VSTR 132
#define PS_W 0
#define KS_W 16896
#define VS_W 25600
#define ATTN_SMEM_WORDS 34048
#define ATTN_SMEM_BYTES (ATTN_SMEM_WORDS * 4)

__global__ __launch_bounds__(256, 1) void attn_mma_kernel(
    const float* __restrict__ gq, const float* __restrict__ gk,
    const float* __restrict__ gv, float* __restrict__ go)
{
    extern __shared__ uint32_t sm[];
    uint32_t* p_s = sm + PS_W;
    uint32_t* k_s = sm + KS_W;
    uint32_t* v_s = sm + VS_W;

    const int bh = blockIdx.y;
    const int b = bh >> 4;
    const int h = bh & 15;
    const int q0 = blockIdx.x * 128;
    const int tid = threadIdx.x;
    const int wid = tid >> 5;
    const int lane = tid & 31;
    const int g = lane >> 2;      // fragment row id
    const int t = lane & 3;       // fragment k id
    const int qrow = wid * 16;    // warp's q base within tile

    const float* qbase = gq + (size_t)b * LSEQ * DMODEL + h * EDIM;
    const float* kbase = gk + (size_t)b * SSEQ * DMODEL + h * EDIM;
    const float* vbase = gv + (size_t)b * SSEQ * DMODEL + h * EDIM;

    // ---- stage Q (scaled, tf32, permuted) into p_s ----
    #pragma unroll
    for (int it = 0; it < 8; it++) {
        const int idx = tid + 256 * it;      // 0..2047
        const int r = idx >> 4;              // 0..127
        const int eq = idx & 15;             // e>>2
        float4 qv = *(const float4*)(qbase + (size_t)(q0 + r) * DMODEL + eq * 4);
        uint32_t* dst = p_s + r * PSTR + eq;
        dst[0]  = f2tf(qv.x * 0.125f);
        dst[16] = f2tf(qv.y * 0.125f);
        dst[32] = f2tf(qv.z * 0.125f);
        dst[48] = f2tf(qv.w * 0.125f);
    }
    __syncthreads();

    // ---- Q fragments to registers (loop-invariant) ----
    uint32_t qa[16], qb[16];
    {
        const uint32_t* r0 = p_s + (qrow + g) * PSTR + t * 16;
        const uint32_t* r1 = p_s + (qrow + g + 8) * PSTR + t * 16;
        #pragma unroll
        for (int u = 0; u < 4; u++) {
            *(uint4*)&qa[u * 4] = *(const uint4*)&r0[u * 4];
            *(uint4*)&qb[u * 4] = *(const uint4*)&r1[u * 4];
        }
    }

    float m0 = -1e30f, m1 = -1e30f, l0 = 0.0f, l1 = 0.0f;
    float av[8][4];
    #pragma unroll
    for (int nt = 0; nt < 8; nt++)
        #pragma unroll
        for (int f = 0; f < 4; f++) av[nt][f] = 0.0f;

    for (int s0 = 0; s0 < SSEQ; s0 += 128) {
        __syncthreads();   // p_s/k_s/v_s free (prev AV + Q-frag reads done)

        // ---- load K tile (tf32, permuted) ----
        #pragma unroll
        for (int it = 0; it < 8; it++) {
            const int idx = tid + 256 * it;
            const int r = idx >> 4;
            const int eq = idx & 15;
            float4 kv = *(const float4*)(kbase + (size_t)(s0 + r) * DMODEL + eq * 4);
            uint32_t* dst = k_s + r * KSTR + eq;
            dst[0]  = f2tf(kv.x);
            dst[16] = f2tf(kv.y);
            dst[32] = f2tf(kv.z);
            dst[48] = f2tf(kv.w);
        }
        // ---- load V tile transposed (tf32, permuted) ----
        #pragma unroll
        for (int it = 0; it < 8; it++) {
            const int idx = tid + 256 * it;
            const int j = idx >> 4;
            const int c0 = (idx & 15) * 4;
            float4 vv = *(const float4*)(vbase + (size_t)(s0 + j) * DMODEL + c0);
            const int off = (j & 3) * 32 + (j >> 2);
            v_s[(c0 + 0) * VSTR + off] = f2tf(vv.x);
            v_s[(c0 + 1) * VSTR + off] = f2tf(vv.y);
            v_s[(c0 + 2) * VSTR + off] = f2tf(vv.z);
            v_s[(c0 + 3) * VSTR + off] = f2tf(vv.w);
        }
        __syncthreads();

        // ---- QK^T: 16 n-tiles x 8 k-steps ----
        float sc[16][4];
        #pragma unroll
        for (int nt = 0; nt < 16; nt++)
            #pragma unroll
            for (int f = 0; f < 4; f++) sc[nt][f] = 0.0f;

        #pragma unroll
        for (int nt = 0; nt < 16; nt++) {
            uint32_t kb[16];
            const uint32_t* kp = k_s + (nt * 8 + g) * KSTR + t * 16;
            #pragma unroll
            for (int u = 0; u < 4; u++)
                *(uint4*)&kb[u * 4] = *(const uint4*)&kp[u * 4];
            #pragma unroll
            for (int ks = 0; ks < 8; ks++)
                mma_tf32(sc[nt], qa[2 * ks], qb[2 * ks], qa[2 * ks + 1], qb[2 * ks + 1],
                         kb[2 * ks], kb[2 * ks + 1]);
        }

        // ---- online softmax on fragments ----
        float tm0 = -1e30f, tm1 = -1e30f;
        #pragma unroll
        for (int nt = 0; nt < 16; nt++) {
            tm0 = fmaxf(tm0, fmaxf(sc[nt][0], sc[nt][1]));
            tm1 = fmaxf(tm1, fmaxf(sc[nt][2], sc[nt][3]));
        }
        tm0 = fmaxf(tm0, __shfl_xor_sync(0xffffffffu, tm0, 1));
        tm0 = fmaxf(tm0, __shfl_xor_sync(0xffffffffu, tm0, 2));
        tm1 = fmaxf(tm1, __shfl_xor_sync(0xffffffffu, tm1, 1));
        tm1 = fmaxf(tm1, __shfl_xor_sync(0xffffffffu, tm1, 2));

        const float nm0 = fmaxf(m0, tm0);
        const float nm1 = fmaxf(m1, tm1);
        const float corr0 = __expf(m0 - nm0);
        const float corr1 = __expf(m1 - nm1);
        m0 = nm0; m1 = nm1;

        float rs0 = 0.0f, rs1 = 0.0f;
        #pragma unroll
        for (int nt = 0; nt < 16; nt++) {
            sc[nt][0] = __expf(sc[nt][0] - m0); rs0 += sc[nt][0];
            sc[nt][1] = __expf(sc[nt][1] - m0); rs0 += sc[nt][1];
            sc[nt][2] = __expf(sc[nt][2] - m1); rs1 += sc[nt][2];
            sc[nt][3] = __expf(sc[nt][3] - m1); rs1 += sc[nt][3];
        }
        rs0 += __shfl_xor_sync(0xffffffffu, rs0, 1);
        rs0 += __shfl_xor_sync(0xffffffffu, rs0, 2);
        rs1 += __shfl_xor_sync(0xffffffffu, rs1, 1);
        rs1 += __shfl_xor_sync(0xffffffffu, rs1, 2);
        l0 = l0 * corr0 + rs0;
        l1 = l1 * corr1 + rs1;

        #pragma unroll
        for (int nt = 0; nt < 8; nt++) {
            av[nt][0] *= corr0; av[nt][1] *= corr0;
            av[nt][2] *= corr1; av[nt][3] *= corr1;
        }

        // ---- store P (tf32, permuted) ----
        #pragma unroll
        for (int nt = 0; nt < 16; nt++) {
            #pragma unroll
            for (int d = 0; d < 2; d++) {
                const int j = nt * 8 + t * 2 + d;
                const int off = (j & 3) * 32 + (j >> 2);
                p_s[(qrow + g) * PSTR + off]     = f2tf(sc[nt][d]);
                p_s[(qrow + g + 8) * PSTR + off] = f2tf(sc[nt][2 + d]);
            }
        }
        __syncthreads();

        // ---- AV: 8 n-tiles x 16 k-steps ----
        uint32_t pa[32], pb[32];
        {
            const uint32_t* r0 = p_s + (qrow + g) * PSTR + t * 32;
            const uint32_t* r1 = p_s + (qrow + g + 8) * PSTR + t * 32;
            #pragma unroll
            for (int u = 0; u < 8; u++) {
                *(uint4*)&pa[u * 4] = *(const uint4*)&r0[u * 4];
                *(uint4*)&pb[u * 4] = *(const uint4*)&r1[u * 4];
            }
        }
        #pragma unroll
        for (int nt = 0; nt < 8; nt++) {
            uint32_t vb[32];
            const uint32_t* vp = v_s + (nt * 8 + g) * VSTR + t * 32;
            #pragma unroll
            for (int u = 0; u < 8; u++)
                *(uint4*)&vb[u * 4] = *(const uint4*)&vp[u * 4];
            #pragma unroll
            for (int ks = 0; ks < 16; ks++)
                mma_tf32(av[nt], pa[2 * ks], pb[2 * ks], pa[2 * ks + 1], pb[2 * ks + 1],
                         vb[2 * ks], vb[2 * ks + 1]);
        }
    }

    // ---- epilogue ----
    const float inv0 = 1.0f / l0;
    const float inv1 = 1.0f / l1;
    #pragma unroll
    for (int nt = 0; nt < 8; nt++) {
        const int c = nt * 8 + t * 2;
        float* o0 = go + (size_t)(b * LSEQ + q0 + qrow + g) * DMODEL + h * EDIM + c;
        float* o1 = go + (size_t)(b * LSEQ + q0 + qrow + g + 8) * DMODEL + h * EDIM + c;
        *(float2*)o0 = make_float2(av[nt][0] * inv0, av[nt][1] * inv0);
        *(float2*)o1 = make_float2(av[nt][2] * inv1, av[nt][3] * inv1);
    }
}

// ---------------------------------------------------------------------------
// launch
// ---------------------------------------------------------------------------
extern "C" void kernel_launch(void* const* d_in, const int* in_sizes, int n_in,
                              void* d_out, int out_size)
{
    (void)in_sizes; (void)n_in; (void)out_size;
    const float* queries = (const float*)d_in[0];
    const float* keys    = (const float*)d_in[1];
    const float* values  = (const float*)d_in[2];
    const float* Wq = (const float*)d_in[3];
    const float* bq = (const float*)d_in[4];
    const float* Wk = (const float*)d_in[5];
    const float* bk = (const float*)d_in[6];
    const float* Wv = (const float*)d_in[7];
    const float* bv = (const float*)d_in[8];
    const float* Wo = (const float*)d_in[9];
    const float* bo = (const float*)d_in[10];
    float* out = (float*)d_out;

    float *q, *k, *v, *attn;
    cudaGetSymbolAddress((void**)&q,    g_q);
    cudaGetSymbolAddress((void**)&k,    g_k);
    cudaGetSymbolAddress((void**)&v,    g_v);
    cudaGetSymbolAddress((void**)&attn, g_attn);

    cudaFuncSetAttribute(attn_mma_kernel,
                         cudaFuncAttributeMaxDynamicSharedMemorySize,
                         ATTN_SMEM_BYTES);

    dim3 gemm_grid(GEMM_N / 128, MTOT / 128);   // (8, 64)
    gemm_tf32_kernel<<<gemm_grid, 256>>>(queries, Wq, bq, q);
    gemm_tf32_kernel<<<gemm_grid, 256>>>(keys,    Wk, bk, k);
    gemm_tf32_kernel<<<gemm_grid, 256>>>(values,  Wv, bv, v);

    dim3 attn_grid(LSEQ / 128, BATCH * NHEAD);  // (16, 64)
    attn_mma_kernel<<<attn_grid, 256, ATTN_SMEM_BYTES>>>(q, k, v, attn);

    gemm_tf32_kernel<<<gemm_grid, 256>>>(attn, Wo, bo, out);
}

// round 8
// speedup vs baseline: 3.0603x; 1.4786x over previous
#include <cuda_runtime.h>
#include <math.h>
#include <stdint.h>

// R8: R7 + granule-swizzled smem layouts in the attention kernel so every
// fragment LDS.128 is bank-conflict-free (R7 ncu: L1=89% => smem-bound).

#define BATCH 4
#define LSEQ  2048
#define SSEQ  2048
#define DMODEL 1024
#define NHEAD 16
#define EDIM  64
#define MTOT  (BATCH * LSEQ)

// ---------------------------------------------------------------------------
// tf32 mma.sync helpers
// ---------------------------------------------------------------------------
__device__ __forceinline__ uint32_t f2tf(float f) {
    uint32_t r; asm("cvt.rna.tf32.f32 %0, %1;" : "=r"(r) : "f"(f));
    return r;
}
__device__ __forceinline__ void mma_tf32(float d[4], uint32_t a0, uint32_t a1,
                                         uint32_t a2, uint32_t a3,
                                         uint32_t b0, uint32_t b1) {
    asm volatile(
        "mma.sync.aligned.m16n8k8.row.col.f32.tf32.tf32.f32 "
        "{%0,%1,%2,%3}, {%4,%5,%6,%7}, {%8,%9}, {%0,%1,%2,%3};"
        : "+f"(d[0]), "+f"(d[1]), "+f"(d[2]), "+f"(d[3])
        : "r"(a0), "r"(a1), "r"(a2), "r"(a3), "r"(b0), "r"(b1));
}

// granule swizzle: rotate each 8-granule block by 2*(block index)
// conflict-free fragment loads for rows with stride == 4 mod 32 words.
__device__ __forceinline__ int swz(int pos) {
    const int g4 = pos >> 2;
    return (((g4 & ~7) | ((g4 + 2 * (g4 >> 3)) & 7)) << 2) | (pos & 3);
}

// ---------------------------------------------------------------------------
// Scratch
// ---------------------------------------------------------------------------
__device__ float g_q[MTOT * DMODEL];
__device__ float g_k[MTOT * DMODEL];
__device__ float g_v[MTOT * DMODEL];
__device__ float g_attn[MTOT * DMODEL];

// ---------------------------------------------------------------------------
// tf32 mma.sync GEMM (unchanged from R6/R7 — proven ~144 us/GEMM)
// ---------------------------------------------------------------------------
#define GEMM_N 1024
#define GEMM_K 1024
#define BK 16
#define ASTR 20
#define BSTR 136

__global__ __launch_bounds__(256, 2) void gemm_tf32_kernel(
    const float* __restrict__ A, const float* __restrict__ W,
    const float* __restrict__ bias, float* __restrict__ C)
{
    __shared__ uint32_t a_s[2][128 * ASTR];
    __shared__ uint32_t b_s[2][BK * BSTR];

    const int tid = threadIdx.x;
    const int wid = tid >> 5;
    const int lane = tid & 31;
    const int gidr = lane >> 2;
    const int tig  = lane & 3;
    const int m_base = blockIdx.y * 128;
    const int n_base = blockIdx.x * 128;
    const int warp_m = (wid & 3) * 32;
    const int warp_n = (wid >> 2) * 64;

    const int ar0 = tid >> 2;
    const int aq  = tid & 3;
    const int br0 = tid >> 5;
    const int bq  = tid & 31;

    float acc[2][8][4];
    #pragma unroll
    for (int ma = 0; ma < 2; ma++)
        #pragma unroll
        for (int na = 0; na < 8; na++)
            #pragma unroll
            for (int f = 0; f < 4; f++) acc[ma][na][f] = 0.0f;

    float4 av[2], bv[2];

    #define LDG_STAGE(t)                                                          \
        do {                                                                      \
            const int k0_ = (t) * BK;                                             \
            av[0] = *(const float4*)(A + (size_t)(m_base + ar0) * GEMM_K + k0_ + aq * 4);       \
            av[1] = *(const float4*)(A + (size_t)(m_base + ar0 + 64) * GEMM_K + k0_ + aq * 4);  \
            bv[0] = *(const float4*)(W + (size_t)(k0_ + br0) * GEMM_N + n_base + bq * 4);       \
            bv[1] = *(const float4*)(W + (size_t)(k0_ + br0 + 8) * GEMM_N + n_base + bq * 4);   \
        } while (0)

    #define STS_STAGE(bf)                                                         \
        do {                                                                      \
            uint32_t* ap0 = &a_s[bf][ar0 * ASTR + aq * 4];                        \
            ap0[0] = f2tf(av[0].x); ap0[1] = f2tf(av[0].y);                       \
            ap0[2] = f2tf(av[0].z); ap0[3] = f2tf(av[0].w);                       \
            uint32_t* ap1 = &a_s[bf][(ar0 + 64) * ASTR + aq * 4];                 \
            ap1[0] = f2tf(av[1].x); ap1[1] = f2tf(av[1].y);                       \
            ap1[2] = f2tf(av[1].z); ap1[3] = f2tf(av[1].w);                       \
            uint4 bw0 = make_uint4(f2tf(bv[0].x), f2tf(bv[0].y),                  \
                                   f2tf(bv[0].z), f2tf(bv[0].w));                 \
            uint4 bw1 = make_uint4(f2tf(bv[1].x), f2tf(bv[1].y),                  \
                                   f2tf(bv[1].z), f2tf(bv[1].w));                 \
            *(uint4*)&b_s[bf][br0 * BSTR + bq * 4]       = bw0;                   \
            *(uint4*)&b_s[bf][(br0 + 8) * BSTR + bq * 4] = bw1;                   \
        } while (0)

    LDG_STAGE(0);
    STS_STAGE(0);
    __syncthreads();

    const int NSTAGE = GEMM_K / BK;
    for (int t = 0; t < NSTAGE; t++) {
        const int buf = t & 1;
        if (t < NSTAGE - 1) LDG_STAGE(t + 1);

        #pragma unroll
        for (int kk = 0; kk < 2; kk++) {
            const int kb = kk * 8;
            uint32_t af[2][4];
            #pragma unroll
            for (int ma = 0; ma < 2; ma++) {
                const uint32_t* ap =
                    &a_s[buf][(warp_m + ma * 16 + gidr) * ASTR + kb + tig];
                af[ma][0] = ap[0];
                af[ma][1] = ap[8 * ASTR];
                af[ma][2] = ap[4];
                af[ma][3] = ap[8 * ASTR + 4];
            }
            #pragma unroll
            for (int na = 0; na < 8; na++) {
                const uint32_t* bp =
                    &b_s[buf][(kb + tig) * BSTR + warp_n + na * 8 + gidr];
                const uint32_t b0 = bp[0];
                const uint32_t b1 = bp[4 * BSTR];
                mma_tf32(acc[0][na], af[0][0], af[0][1], af[0][2], af[0][3], b0, b1);
                mma_tf32(acc[1][na], af[1][0], af[1][1], af[1][2], af[1][3], b0, b1);
            }
        }

        if (t < NSTAGE - 1) {
            STS_STAGE((t + 1) & 1);
            __syncthreads();
        }
    }

    #pragma unroll
    for (int na = 0; na < 8; na++) {
        const int col = n_base + warp_n + na * 8 + tig * 2;
        const float bx = __ldg(bias + col);
        const float by = __ldg(bias + col + 1);
        #pragma unroll
        for (int ma = 0; ma < 2; ma++) {
            const int r0 = m_base + warp_m + ma * 16 + gidr;
            float2 lo = make_float2(acc[ma][na][0] + bx, acc[ma][na][1] + by);
            float2 hi = make_float2(acc[ma][na][2] + bx, acc[ma][na][3] + by);
            *(float2*)(C + (size_t)r0 * GEMM_N + col)       = lo;
            *(float2*)(C + (size_t)(r0 + 8) * GEMM_N + col) = hi;
        }
    }
}

// ---------------------------------------------------------------------------
// Flash attention via tf32 mma.sync with conflict-free swizzled smem.
// CTA: 128 q-rows x 128 S-tile, 8 warps. Layout strides in words:
//   p_s / q staging: [row:128][128 perm j or e] stride 132
//   k_s            : [s:128][64 perm e]        stride 68
//   v_s            : [c:64][128 perm j]        stride 132
// All within-row positions pass through swz() at store AND load.
// ---------------------------------------------------------------------------
#define PSTR 132
#define KSTR 68
#define VSTR 132
#define PS_W 0
#define KS_W 16896
#define VS_W 25600
#define ATTN_SMEM_WORDS 34048
#define ATTN_SMEM_BYTES (ATTN_SMEM_WORDS * 4)

__global__ __launch_bounds__(256, 1) void attn_mma_kernel(
    const float* __restrict__ gq, const float* __restrict__ gk,
    const float* __restrict__ gv, float* __restrict__ go)
{
    extern __shared__ uint32_t sm[];
    uint32_t* p_s = sm + PS_W;
    uint32_t* k_s = sm + KS_W;
    uint32_t* v_s = sm + VS_W;

    const int bh = blockIdx.y;
    const int b = bh >> 4;
    const int h = bh & 15;
    const int q0 = blockIdx.x * 128;
    const int tid = threadIdx.x;
    const int wid = tid >> 5;
    const int lane = tid & 31;
    const int g = lane >> 2;
    const int t = lane & 3;
    const int qrow = wid * 16;

    const float* qbase = gq + (size_t)b * LSEQ * DMODEL + h * EDIM;
    const float* kbase = gk + (size_t)b * SSEQ * DMODEL + h * EDIM;
    const float* vbase = gv + (size_t)b * SSEQ * DMODEL + h * EDIM;

    // per-thread loop-invariant swizzled offsets
    int fo16[4], fo32[8];
    #pragma unroll
    for (int u = 0; u < 4; u++) fo16[u] = swz(t * 16 + u * 4);
    #pragma unroll
    for (int u = 0; u < 8; u++) fo32[u] = swz(t * 32 + u * 4);

    // staging constants: eq = tid&15 invariant across the it-loop
    const int eqc = tid & 15;
    int stg16[4];
    #pragma unroll
    for (int c = 0; c < 4; c++) stg16[c] = swz(c * 16 + eqc);

    // ---- stage Q (scaled, tf32, swizzled perm) into p_s ----
    #pragma unroll
    for (int it = 0; it < 8; it++) {
        const int r = (tid >> 4) + 16 * it;
        float4 qv = *(const float4*)(qbase + (size_t)(q0 + r) * DMODEL + eqc * 4);
        uint32_t* dst = p_s + r * PSTR;
        dst[stg16[0]] = f2tf(qv.x * 0.125f);
        dst[stg16[1]] = f2tf(qv.y * 0.125f);
        dst[stg16[2]] = f2tf(qv.z * 0.125f);
        dst[stg16[3]] = f2tf(qv.w * 0.125f);
    }
    __syncthreads();

    // ---- Q fragments to registers (loop-invariant) ----
    uint32_t qa[16], qb[16];
    {
        const uint32_t* r0 = p_s + (qrow + g) * PSTR;
        const uint32_t* r1 = p_s + (qrow + g + 8) * PSTR;
        #pragma unroll
        for (int u = 0; u < 4; u++) {
            *(uint4*)&qa[u * 4] = *(const uint4*)&r0[fo16[u]];
            *(uint4*)&qb[u * 4] = *(const uint4*)&r1[fo16[u]];
        }
    }

    float m0 = -1e30f, m1 = -1e30f, l0 = 0.0f, l1 = 0.0f;
    float av[8][4];
    #pragma unroll
    for (int nt = 0; nt < 8; nt++)
        #pragma unroll
        for (int f = 0; f < 4; f++) av[nt][f] = 0.0f;

    // P-store swizzle bases: j = 8nt + 2t + d -> pos = ((2t+d)&3)*32 + 2nt + ((2t+d)>>2)
    const int pj0 = ((2 * t) & 3) * 32 + ((2 * t) >> 2);
    const int pj1 = ((2 * t + 1) & 3) * 32 + ((2 * t + 1) >> 2);

    for (int s0 = 0; s0 < SSEQ; s0 += 128) {
        __syncthreads();

        // ---- stage K tile ----
        #pragma unroll
        for (int it = 0; it < 8; it++) {
            const int r = (tid >> 4) + 16 * it;
            float4 kv = *(const float4*)(kbase + (size_t)(s0 + r) * DMODEL + eqc * 4);
            uint32_t* dst = k_s + r * KSTR;
            dst[stg16[0]] = f2tf(kv.x);
            dst[stg16[1]] = f2tf(kv.y);
            dst[stg16[2]] = f2tf(kv.z);
            dst[stg16[3]] = f2tf(kv.w);
        }
        // ---- stage V tile transposed ----
        #pragma unroll
        for (int it = 0; it < 8; it++) {
            const int j = (tid >> 4) + 16 * it;
            const int c0 = eqc * 4;
            float4 vv = *(const float4*)(vbase + (size_t)(s0 + j) * DMODEL + c0);
            const int off = swz((j & 3) * 32 + (j >> 2));
            v_s[(c0 + 0) * VSTR + off] = f2tf(vv.x);
            v_s[(c0 + 1) * VSTR + off] = f2tf(vv.y);
            v_s[(c0 + 2) * VSTR + off] = f2tf(vv.z);
            v_s[(c0 + 3) * VSTR + off] = f2tf(vv.w);
        }
        __syncthreads();

        // ---- QK^T: 16 n-tiles x 8 k-steps ----
        float sc[16][4];
        #pragma unroll
        for (int nt = 0; nt < 16; nt++)
            #pragma unroll
            for (int f = 0; f < 4; f++) sc[nt][f] = 0.0f;

        #pragma unroll
        for (int nt = 0; nt < 16; nt++) {
            uint32_t kb[16];
            const uint32_t* kp = k_s + (nt * 8 + g) * KSTR;
            #pragma unroll
            for (int u = 0; u < 4; u++)
                *(uint4*)&kb[u * 4] = *(const uint4*)&kp[fo16[u]];
            #pragma unroll
            for (int ks = 0; ks < 8; ks++)
                mma_tf32(sc[nt], qa[2 * ks], qb[2 * ks], qa[2 * ks + 1], qb[2 * ks + 1],
                         kb[2 * ks], kb[2 * ks + 1]);
        }

        // ---- online softmax on fragments ----
        float tm0 = -1e30f, tm1 = -1e30f;
        #pragma unroll
        for (int nt = 0; nt < 16; nt++) {
            tm0 = fmaxf(tm0, fmaxf(sc[nt][0], sc[nt][1]));
            tm1 = fmaxf(tm1, fmaxf(sc[nt][2], sc[nt][3]));
        }
        tm0 = fmaxf(tm0, __shfl_xor_sync(0xffffffffu, tm0, 1));
        tm0 = fmaxf(tm0, __shfl_xor_sync(0xffffffffu, tm0, 2));
        tm1 = fmaxf(tm1, __shfl_xor_sync(0xffffffffu, tm1, 1));
        tm1 = fmaxf(tm1, __shfl_xor_sync(0xffffffffu, tm1, 2));

        const float nm0 = fmaxf(m0, tm0);
        const float nm1 = fmaxf(m1, tm1);
        const float corr0 = __expf(m0 - nm0);
        const float corr1 = __expf(m1 - nm1);
        m0 = nm0; m1 = nm1;

        float rs0 = 0.0f, rs1 = 0.0f;
        #pragma unroll
        for (int nt = 0; nt < 16; nt++) {
            sc[nt][0] = __expf(sc[nt][0] - m0); rs0 += sc[nt][0];
            sc[nt][1] = __expf(sc[nt][1] - m0); rs0 += sc[nt][1];
            sc[nt][2] = __expf(sc[nt][2] - m1); rs1 += sc[nt][2];
            sc[nt][3] = __expf(sc[nt][3] - m1); rs1 += sc[nt][3];
        }
        rs0 += __shfl_xor_sync(0xffffffffu, rs0, 1);
        rs0 += __shfl_xor_sync(0xffffffffu, rs0, 2);
        rs1 += __shfl_xor_sync(0xffffffffu, rs1, 1);
        rs1 += __shfl_xor_sync(0xffffffffu, rs1, 2);
        l0 = l0 * corr0 + rs0;
        l1 = l1 * corr1 + rs1;

        #pragma unroll
        for (int nt = 0; nt < 8; nt++) {
            av[nt][0] *= corr0; av[nt][1] *= corr0;
            av[nt][2] *= corr1; av[nt][3] *= corr1;
        }

        // ---- store P (tf32, swizzled perm) ----
        #pragma unroll
        for (int nt = 0; nt < 16; nt++) {
            const int o0 = swz(pj0 + 2 * nt);
            const int o1 = swz(pj1 + 2 * nt);
            p_s[(qrow + g) * PSTR + o0]     = f2tf(sc[nt][0]);
            p_s[(qrow + g) * PSTR + o1]     = f2tf(sc[nt][1]);
            p_s[(qrow + g + 8) * PSTR + o0] = f2tf(sc[nt][2]);
            p_s[(qrow + g + 8) * PSTR + o1] = f2tf(sc[nt][3]);
        }
        __syncthreads();

        // ---- AV: 8 n-tiles x 16 k-steps ----
        uint32_t pa[32], pb[32];
        {
            const uint32_t* r0 = p_s + (qrow + g) * PSTR;
            const uint32_t* r1 = p_s + (qrow + g + 8) * PSTR;
            #pragma unroll
            for (int u = 0; u < 8; u++) {
                *(uint4*)&pa[u * 4] = *(const uint4*)&r0[fo32[u]];
                *(uint4*)&pb[u * 4] = *(const uint4*)&r1[fo32[u]];
            }
        }
        #pragma unroll
        for (int nt = 0; nt < 8; nt++) {
            uint32_t vb[32];
            const uint32_t* vp = v_s + (nt * 8 + g) * VSTR;
            #pragma unroll
            for (int u = 0; u < 8; u++)
                *(uint4*)&vb[u * 4] = *(const uint4*)&vp[fo32[u]];
            #pragma unroll
            for (int ks = 0; ks < 16; ks++)
                mma_tf32(av[nt], pa[2 * ks], pb[2 * ks], pa[2 * ks + 1], pb[2 * ks + 1],
                         vb[2 * ks], vb[2 * ks + 1]);
        }
    }

    // ---- epilogue ----
    const float inv0 = 1.0f / l0;
    const float inv1 = 1.0f / l1;
    #pragma unroll
    for (int nt = 0; nt < 8; nt++) {
        const int c = nt * 8 + t * 2;
        float* o0 = go + (size_t)(b * LSEQ + q0 + qrow + g) * DMODEL + h * EDIM + c;
        float* o1 = go + (size_t)(b * LSEQ + q0 + qrow + g + 8) * DMODEL + h * EDIM + c;
        *(float2*)o0 = make_float2(av[nt][0] * inv0, av[nt][1] * inv0);
        *(float2*)o1 = make_float2(av[nt][2] * inv1, av[nt][3] * inv1);
    }
}

// ---------------------------------------------------------------------------
// launch
// ---------------------------------------------------------------------------
extern "C" void kernel_launch(void* const* d_in, const int* in_sizes, int n_in,
                              void* d_out, int out_size)
{
    (void)in_sizes; (void)n_in; (void)out_size;
    const float* queries = (const float*)d_in[0];
    const float* keys    = (const float*)d_in[1];
    const float* values  = (const float*)d_in[2];
    const float* Wq = (const float*)d_in[3];
    const float* bq = (const float*)d_in[4];
    const float* Wk = (const float*)d_in[5];
    const float* bk = (const float*)d_in[6];
    const float* Wv = (const float*)d_in[7];
    const float* bv = (const float*)d_in[8];
    const float* Wo = (const float*)d_in[9];
    const float* bo = (const float*)d_in[10];
    float* out = (float*)d_out;

    float *q, *k, *v, *attn;
    cudaGetSymbolAddress((void**)&q,    g_q);
    cudaGetSymbolAddress((void**)&k,    g_k);
    cudaGetSymbolAddress((void**)&v,    g_v);
    cudaGetSymbolAddress((void**)&attn, g_attn);

    cudaFuncSetAttribute(attn_mma_kernel,
                         cudaFuncAttributeMaxDynamicSharedMemorySize,
                         ATTN_SMEM_BYTES);

    dim3 gemm_grid(GEMM_N / 128, MTOT / 128);   // (8, 64)
    gemm_tf32_kernel<<<gemm_grid, 256>>>(queries, Wq, bq, q);
    gemm_tf32_kernel<<<gemm_grid, 256>>>(keys,    Wk, bk, k);
    gemm_tf32_kernel<<<gemm_grid, 256>>>(values,  Wv, bv, v);

    dim3 attn_grid(LSEQ / 128, BATCH * NHEAD);  // (16, 64)
    attn_mma_kernel<<<attn_grid, 256, ATTN_SMEM_BYTES>>>(q, k, v, attn);

    gemm_tf32_kernel<<<gemm_grid, 256>>>(attn, Wo, bo, out);
}

// round 9
// speedup vs baseline: 3.2299x; 1.0554x over previous
#include <cuda_runtime.h>
#include <math.h>
#include <stdint.h>

// R9: cp.async 4-stage pipelined tf32 GEMMs (weights pre-converted to tf32,
// A converted at fragment load), QKV batched via grid.z. Attention = R8.

#define BATCH 4
#define LSEQ  2048
#define SSEQ  2048
#define DMODEL 1024
#define NHEAD 16
#define EDIM  64
#define MTOT  (BATCH * LSEQ)

// ---------------------------------------------------------------------------
// helpers
// ---------------------------------------------------------------------------
__device__ __forceinline__ uint32_t f2tf(float f) {
    uint32_t r; asm("cvt.rna.tf32.f32 %0, %1;" : "=r"(r) : "f"(f));
    return r;
}
__device__ __forceinline__ void mma_tf32(float d[4], uint32_t a0, uint32_t a1,
                                         uint32_t a2, uint32_t a3,
                                         uint32_t b0, uint32_t b1) {
    asm volatile(
        "mma.sync.aligned.m16n8k8.row.col.f32.tf32.tf32.f32 "
        "{%0,%1,%2,%3}, {%4,%5,%6,%7}, {%8,%9}, {%0,%1,%2,%3};"
        : "+f"(d[0]), "+f"(d[1]), "+f"(d[2]), "+f"(d[3])
        : "r"(a0), "r"(a1), "r"(a2), "r"(a3), "r"(b0), "r"(b1));
}
__device__ __forceinline__ uint32_t smem_u32(const void* p) {
    uint32_t a;
    asm("{ .reg .u64 t; cvta.to.shared.u64 t, %1; cvt.u32.u64 %0, t; }" : "=r"(a) : "l"(p));
    return a;
}
__device__ __forceinline__ void cpa16(uint32_t dst, const void* src) {
    asm volatile("cp.async.cg.shared.global [%0], [%1], 16;" :: "r"(dst), "l"(src));
}
__device__ __forceinline__ void cpa_commit() {
    asm volatile("cp.async.commit_group;" ::: "memory");
}
__device__ __forceinline__ void cpa_wait2() {
    asm volatile("cp.async.wait_group 2;" ::: "memory");
}
__device__ __forceinline__ void cpa_wait0() {
    asm volatile("cp.async.wait_group 0;" ::: "memory");
}
// granule swizzle (attention): rotate each 8-granule block by 2*(block idx)
__device__ __forceinline__ int swz(int pos) {
    const int g4 = pos >> 2;
    return (((g4 & ~7) | ((g4 + 2 * (g4 >> 3)) & 7)) << 2) | (pos & 3);
}

// ---------------------------------------------------------------------------
// Scratch
// ---------------------------------------------------------------------------
__device__ float g_q[MTOT * DMODEL];
__device__ float g_k[MTOT * DMODEL];
__device__ float g_v[MTOT * DMODEL];
__device__ float g_attn[MTOT * DMODEL];
__device__ float g_wq[DMODEL * DMODEL];
__device__ float g_wk[DMODEL * DMODEL];
__device__ float g_wv[DMODEL * DMODEL];
__device__ float g_wo[DMODEL * DMODEL];

// ---------------------------------------------------------------------------
// weight pre-convert: dst = tf32_rna(src), 1M floats per z
// ---------------------------------------------------------------------------
struct WC { const float* src[4]; float* dst[4]; };
__global__ __launch_bounds__(256) void wconv_kernel(WC p) {
    const float* s = p.src[blockIdx.y];
    float* d = p.dst[blockIdx.y];
    const int i = (blockIdx.x * 256 + threadIdx.x) * 4;
    float4 v = *(const float4*)(s + i);
    v.x = __uint_as_float(f2tf(v.x));
    v.y = __uint_as_float(f2tf(v.y));
    v.z = __uint_as_float(f2tf(v.z));
    v.w = __uint_as_float(f2tf(v.w));
    *(float4*)(d + i) = v;
}

// ---------------------------------------------------------------------------
// tf32 GEMM, cp.async 4-stage: C[8192,1024] = A @ Wtf32 + bias
// A raw fp32 in smem (cvt at fragment load); W pre-converted tf32 bits.
// 128x128 tile, BK=16, 256 thr, batched over grid.z.
// ---------------------------------------------------------------------------
#define GEMM_N 1024
#define GEMM_K 1024
#define BK 16
#define ASTR 20
#define BSTR 136
#define A_STG (128 * ASTR)          // 2560 words
#define B_STG (BK * BSTR)           // 2176 words
#define GEMM_SMEM_WORDS (4 * A_STG + 4 * B_STG)
#define GEMM_SMEM_BYTES (GEMM_SMEM_WORDS * 4)

struct G3 { const float* A[3]; const float* W[3]; const float* B[3]; float* C[3]; };

__global__ __launch_bounds__(256, 2) void gemm_tf32_kernel(G3 p) {
    extern __shared__ uint32_t dsm[];
    const int z = blockIdx.z;
    const float* __restrict__ A = p.A[z];
    const float* __restrict__ W = p.W[z];
    const float* __restrict__ bias = p.B[z];
    float* __restrict__ C = p.C[z];

    const int tid = threadIdx.x;
    const int wid = tid >> 5;
    const int lane = tid & 31;
    const int gidr = lane >> 2;
    const int tig  = lane & 3;
    const int m_base = blockIdx.y * 128;
    const int n_base = blockIdx.x * 128;
    const int warp_m = (wid & 3) * 32;
    const int warp_n = (wid >> 2) * 64;

    const int ar0 = tid >> 2;
    const int aq  = tid & 3;
    const int br0 = tid >> 5;
    const int bq  = tid & 31;

    const uint32_t smem_base = smem_u32(dsm);

    // cp.async dst addresses per stage (bytes)
    const uint32_t a_dst0 = smem_base + (ar0 * ASTR + aq * 4) * 4;
    const uint32_t a_dst1 = smem_base + ((ar0 + 64) * ASTR + aq * 4) * 4;
    const uint32_t b_dst0 = smem_base + (4 * A_STG + br0 * BSTR + bq * 4) * 4;
    const uint32_t b_dst1 = smem_base + (4 * A_STG + (br0 + 8) * BSTR + bq * 4) * 4;

    const float* a_src0 = A + (size_t)(m_base + ar0) * GEMM_K + aq * 4;
    const float* a_src1 = A + (size_t)(m_base + ar0 + 64) * GEMM_K + aq * 4;
    const float* b_src0 = W + (size_t)br0 * GEMM_N + n_base + bq * 4;
    const float* b_src1 = W + (size_t)(br0 + 8) * GEMM_N + n_base + bq * 4;

    float acc[2][8][4];
    #pragma unroll
    for (int ma = 0; ma < 2; ma++)
        #pragma unroll
        for (int na = 0; na < 8; na++)
            #pragma unroll
            for (int f = 0; f < 4; f++) acc[ma][na][f] = 0.0f;

    const int NSTAGE = GEMM_K / BK;   // 64

    // prologue: stages 0,1,2
    #pragma unroll
    for (int s = 0; s < 3; s++) {
        const uint32_t ao = s * A_STG * 4;
        const uint32_t bo = s * B_STG * 4;
        cpa16(a_dst0 + ao, a_src0 + s * BK);
        cpa16(a_dst1 + ao, a_src1 + s * BK);
        cpa16(b_dst0 + bo, b_src0 + (size_t)s * BK * GEMM_N);
        cpa16(b_dst1 + bo, b_src1 + (size_t)s * BK * GEMM_N);
        cpa_commit();
    }

    for (int t = 0; t < NSTAGE; t++) {
        if (t < NSTAGE - 3) cpa_wait2(); else cpa_wait0();
        __syncthreads();

        // issue stage t+3 (buffers (t+3)&3 == (t-1)&3, free after this sync)
        if (t + 3 < NSTAGE) {
            const int s = t + 3;
            const int sb = s & 3;
            const uint32_t ao = sb * A_STG * 4;
            const uint32_t bo = sb * B_STG * 4;
            cpa16(a_dst0 + ao, a_src0 + s * BK);
            cpa16(a_dst1 + ao, a_src1 + s * BK);
            cpa16(b_dst0 + bo, b_src0 + (size_t)s * BK * GEMM_N);
            cpa16(b_dst1 + bo, b_src1 + (size_t)s * BK * GEMM_N);
        }
        cpa_commit();

        const uint32_t* a_s = dsm + (t & 3) * A_STG;
        const uint32_t* b_s = dsm + 4 * A_STG + (t & 3) * B_STG;

        #pragma unroll
        for (int kk = 0; kk < 2; kk++) {
            const int kb = kk * 8;
            uint32_t af[2][4];
            #pragma unroll
            for (int ma = 0; ma < 2; ma++) {
                const uint32_t* ap = &a_s[(warp_m + ma * 16 + gidr) * ASTR + kb + tig];
                af[ma][0] = f2tf(__uint_as_float(ap[0]));
                af[ma][1] = f2tf(__uint_as_float(ap[8 * ASTR]));
                af[ma][2] = f2tf(__uint_as_float(ap[4]));
                af[ma][3] = f2tf(__uint_as_float(ap[8 * ASTR + 4]));
            }
            #pragma unroll
            for (int na = 0; na < 8; na++) {
                const uint32_t* bp = &b_s[(kb + tig) * BSTR + warp_n + na * 8 + gidr];
                const uint32_t b0 = bp[0];
                const uint32_t b1 = bp[4 * BSTR];
                mma_tf32(acc[0][na], af[0][0], af[0][1], af[0][2], af[0][3], b0, b1);
                mma_tf32(acc[1][na], af[1][0], af[1][1], af[1][2], af[1][3], b0, b1);
            }
        }
        __syncthreads();
    }

    #pragma unroll
    for (int na = 0; na < 8; na++) {
        const int col = n_base + warp_n + na * 8 + tig * 2;
        const float bx = __ldg(bias + col);
        const float by = __ldg(bias + col + 1);
        #pragma unroll
        for (int ma = 0; ma < 2; ma++) {
            const int r0 = m_base + warp_m + ma * 16 + gidr;
            float2 lo = make_float2(acc[ma][na][0] + bx, acc[ma][na][1] + by);
            float2 hi = make_float2(acc[ma][na][2] + bx, acc[ma][na][3] + by);
            *(float2*)(C + (size_t)r0 * GEMM_N + col)       = lo;
            *(float2*)(C + (size_t)(r0 + 8) * GEMM_N + col) = hi;
        }
    }
}

// ---------------------------------------------------------------------------
// Flash attention via tf32 mma.sync, swizzled smem (unchanged from R8)
// ---------------------------------------------------------------------------
#define PSTR 132
#define KSTR 68
#define VSTR 132
#define PS_W 0
#define KS_W 16896
#define VS_W 25600
#define ATTN_SMEM_WORDS 34048
#define ATTN_SMEM_BYTES (ATTN_SMEM_WORDS * 4)

__global__ __launch_bounds__(256, 1) void attn_mma_kernel(
    const float* __restrict__ gq, const float* __restrict__ gk,
    const float* __restrict__ gv, float* __restrict__ go)
{
    extern __shared__ uint32_t sm[];
    uint32_t* p_s = sm + PS_W;
    uint32_t* k_s = sm + KS_W;
    uint32_t* v_s = sm + VS_W;

    const int bh = blockIdx.y;
    const int b = bh >> 4;
    const int h = bh & 15;
    const int q0 = blockIdx.x * 128;
    const int tid = threadIdx.x;
    const int wid = tid >> 5;
    const int lane = tid & 31;
    const int g = lane >> 2;
    const int t = lane & 3;
    const int qrow = wid * 16;

    const float* qbase = gq + (size_t)b * LSEQ * DMODEL + h * EDIM;
    const float* kbase = gk + (size_t)b * SSEQ * DMODEL + h * EDIM;
    const float* vbase = gv + (size_t)b * SSEQ * DMODEL + h * EDIM;

    int fo16[4], fo32[8];
    #pragma unroll
    for (int u = 0; u < 4; u++) fo16[u] = swz(t * 16 + u * 4);
    #pragma unroll
    for (int u = 0; u < 8; u++) fo32[u] = swz(t * 32 + u * 4);

    const int eqc = tid & 15;
    int stg16[4];
    #pragma unroll
    for (int c = 0; c < 4; c++) stg16[c] = swz(c * 16 + eqc);

    #pragma unroll
    for (int it = 0; it < 8; it++) {
        const int r = (tid >> 4) + 16 * it;
        float4 qv = *(const float4*)(qbase + (size_t)(q0 + r) * DMODEL + eqc * 4);
        uint32_t* dst = p_s + r * PSTR;
        dst[stg16[0]] = f2tf(qv.x * 0.125f);
        dst[stg16[1]] = f2tf(qv.y * 0.125f);
        dst[stg16[2]] = f2tf(qv.z * 0.125f);
        dst[stg16[3]] = f2tf(qv.w * 0.125f);
    }
    __syncthreads();

    uint32_t qa[16], qb[16];
    {
        const uint32_t* r0 = p_s + (qrow + g) * PSTR;
        const uint32_t* r1 = p_s + (qrow + g + 8) * PSTR;
        #pragma unroll
        for (int u = 0; u < 4; u++) {
            *(uint4*)&qa[u * 4] = *(const uint4*)&r0[fo16[u]];
            *(uint4*)&qb[u * 4] = *(const uint4*)&r1[fo16[u]];
        }
    }

    float m0 = -1e30f, m1 = -1e30f, l0 = 0.0f, l1 = 0.0f;
    float av[8][4];
    #pragma unroll
    for (int nt = 0; nt < 8; nt++)
        #pragma unroll
        for (int f = 0; f < 4; f++) av[nt][f] = 0.0f;

    const int pj0 = ((2 * t) & 3) * 32 + ((2 * t) >> 2);
    const int pj1 = ((2 * t + 1) & 3) * 32 + ((2 * t + 1) >> 2);

    for (int s0 = 0; s0 < SSEQ; s0 += 128) {
        __syncthreads();

        #pragma unroll
        for (int it = 0; it < 8; it++) {
            const int r = (tid >> 4) + 16 * it;
            float4 kv = *(const float4*)(kbase + (size_t)(s0 + r) * DMODEL + eqc * 4);
            uint32_t* dst = k_s + r * KSTR;
            dst[stg16[0]] = f2tf(kv.x);
            dst[stg16[1]] = f2tf(kv.y);
            dst[stg16[2]] = f2tf(kv.z);
            dst[stg16[3]] = f2tf(kv.w);
        }
        #pragma unroll
        for (int it = 0; it < 8; it++) {
            const int j = (tid >> 4) + 16 * it;
            const int c0 = eqc * 4;
            float4 vv = *(const float4*)(vbase + (size_t)(s0 + j) * DMODEL + c0);
            const int off = swz((j & 3) * 32 + (j >> 2));
            v_s[(c0 + 0) * VSTR + off] = f2tf(vv.x);
            v_s[(c0 + 1) * VSTR + off] = f2tf(vv.y);
            v_s[(c0 + 2) * VSTR + off] = f2tf(vv.z);
            v_s[(c0 + 3) * VSTR + off] = f2tf(vv.w);
        }
        __syncthreads();

        float sc[16][4];
        #pragma unroll
        for (int nt = 0; nt < 16; nt++)
            #pragma unroll
            for (int f = 0; f < 4; f++) sc[nt][f] = 0.0f;

        #pragma unroll
        for (int nt = 0; nt < 16; nt++) {
            uint32_t kb[16];
            const uint32_t* kp = k_s + (nt * 8 + g) * KSTR;
            #pragma unroll
            for (int u = 0; u < 4; u++)
                *(uint4*)&kb[u * 4] = *(const uint4*)&kp[fo16[u]];
            #pragma unroll
            for (int ks = 0; ks < 8; ks++)
                mma_tf32(sc[nt], qa[2 * ks], qb[2 * ks], qa[2 * ks + 1], qb[2 * ks + 1],
                         kb[2 * ks], kb[2 * ks + 1]);
        }

        float tm0 = -1e30f, tm1 = -1e30f;
        #pragma unroll
        for (int nt = 0; nt < 16; nt++) {
            tm0 = fmaxf(tm0, fmaxf(sc[nt][0], sc[nt][1]));
            tm1 = fmaxf(tm1, fmaxf(sc[nt][2], sc[nt][3]));
        }
        tm0 = fmaxf(tm0, __shfl_xor_sync(0xffffffffu, tm0, 1));
        tm0 = fmaxf(tm0, __shfl_xor_sync(0xffffffffu, tm0, 2));
        tm1 = fmaxf(tm1, __shfl_xor_sync(0xffffffffu, tm1, 1));
        tm1 = fmaxf(tm1, __shfl_xor_sync(0xffffffffu, tm1, 2));

        const float nm0 = fmaxf(m0, tm0);
        const float nm1 = fmaxf(m1, tm1);
        const float corr0 = __expf(m0 - nm0);
        const float corr1 = __expf(m1 - nm1);
        m0 = nm0; m1 = nm1;

        float rs0 = 0.0f, rs1 = 0.0f;
        #pragma unroll
        for (int nt = 0; nt < 16; nt++) {
            sc[nt][0] = __expf(sc[nt][0] - m0); rs0 += sc[nt][0];
            sc[nt][1] = __expf(sc[nt][1] - m0); rs0 += sc[nt][1];
            sc[nt][2] = __expf(sc[nt][2] - m1); rs1 += sc[nt][2];
            sc[nt][3] = __expf(sc[nt][3] - m1); rs1 += sc[nt][3];
        }
        rs0 += __shfl_xor_sync(0xffffffffu, rs0, 1);
        rs0 += __shfl_xor_sync(0xffffffffu, rs0, 2);
        rs1 += __shfl_xor_sync(0xffffffffu, rs1, 1);
        rs1 += __shfl_xor_sync(0xffffffffu, rs1, 2);
        l0 = l0 * corr0 + rs0;
        l1 = l1 * corr1 + rs1;

        #pragma unroll
        for (int nt = 0; nt < 8; nt++) {
            av[nt][0] *= corr0; av[nt][1] *= corr0;
            av[nt][2] *= corr1; av[nt][3] *= corr1;
        }

        #pragma unroll
        for (int nt = 0; nt < 16; nt++) {
            const int o0 = swz(pj0 + 2 * nt);
            const int o1 = swz(pj1 + 2 * nt);
            p_s[(qrow + g) * PSTR + o0]     = f2tf(sc[nt][0]);
            p_s[(qrow + g) * PSTR + o1]     = f2tf(sc[nt][1]);
            p_s[(qrow + g + 8) * PSTR + o0] = f2tf(sc[nt][2]);
            p_s[(qrow + g + 8) * PSTR + o1] = f2tf(sc[nt][3]);
        }
        __syncthreads();

        uint32_t pa[32], pb[32];
        {
            const uint32_t* r0 = p_s + (qrow + g) * PSTR;
            const uint32_t* r1 = p_s + (qrow + g + 8) * PSTR;
            #pragma unroll
            for (int u = 0; u < 8; u++) {
                *(uint4*)&pa[u * 4] = *(const uint4*)&r0[fo32[u]];
                *(uint4*)&pb[u * 4] = *(const uint4*)&r1[fo32[u]];
            }
        }
        #pragma unroll
        for (int nt = 0; nt < 8; nt++) {
            uint32_t vb[32];
            const uint32_t* vp = v_s + (nt * 8 + g) * VSTR;
            #pragma unroll
            for (int u = 0; u < 8; u++)
                *(uint4*)&vb[u * 4] = *(const uint4*)&vp[fo32[u]];
            #pragma unroll
            for (int ks = 0; ks < 16; ks++)
                mma_tf32(av[nt], pa[2 * ks], pb[2 * ks], pa[2 * ks + 1], pb[2 * ks + 1],
                         vb[2 * ks], vb[2 * ks + 1]);
        }
    }

    const float inv0 = 1.0f / l0;
    const float inv1 = 1.0f / l1;
    #pragma unroll
    for (int nt = 0; nt < 8; nt++) {
        const int c = nt * 8 + t * 2;
        float* o0 = go + (size_t)(b * LSEQ + q0 + qrow + g) * DMODEL + h * EDIM + c;
        float* o1 = go + (size_t)(b * LSEQ + q0 + qrow + g + 8) * DMODEL + h * EDIM + c;
        *(float2*)o0 = make_float2(av[nt][0] * inv0, av[nt][1] * inv0);
        *(float2*)o1 = make_float2(av[nt][2] * inv1, av[nt][3] * inv1);
    }
}

// ---------------------------------------------------------------------------
// launch
// ---------------------------------------------------------------------------
extern "C" void kernel_launch(void* const* d_in, const int* in_sizes, int n_in,
                              void* d_out, int out_size)
{
    (void)in_sizes; (void)n_in; (void)out_size;
    const float* queries = (const float*)d_in[0];
    const float* keys    = (const float*)d_in[1];
    const float* values  = (const float*)d_in[2];
    const float* Wq = (const float*)d_in[3];
    const float* bq = (const float*)d_in[4];
    const float* Wk = (const float*)d_in[5];
    const float* bk = (const float*)d_in[6];
    const float* Wv = (const float*)d_in[7];
    const float* bv = (const float*)d_in[8];
    const float* Wo = (const float*)d_in[9];
    const float* bo = (const float*)d_in[10];
    float* out = (float*)d_out;

    float *q, *k, *v, *attn, *wq, *wk, *wv, *wo;
    cudaGetSymbolAddress((void**)&q,    g_q);
    cudaGetSymbolAddress((void**)&k,    g_k);
    cudaGetSymbolAddress((void**)&v,    g_v);
    cudaGetSymbolAddress((void**)&attn, g_attn);
    cudaGetSymbolAddress((void**)&wq,   g_wq);
    cudaGetSymbolAddress((void**)&wk,   g_wk);
    cudaGetSymbolAddress((void**)&wv,   g_wv);
    cudaGetSymbolAddress((void**)&wo,   g_wo);

    cudaFuncSetAttribute(gemm_tf32_kernel,
                         cudaFuncAttributeMaxDynamicSharedMemorySize,
                         GEMM_SMEM_BYTES);
    cudaFuncSetAttribute(attn_mma_kernel,
                         cudaFuncAttributeMaxDynamicSharedMemorySize,
                         ATTN_SMEM_BYTES);

    // 1. pre-convert weights to tf32
    WC wc;
    wc.src[0] = Wq; wc.src[1] = Wk; wc.src[2] = Wv; wc.src[3] = Wo;
    wc.dst[0] = wq; wc.dst[1] = wk; wc.dst[2] = wv; wc.dst[3] = wo;
    wconv_kernel<<<dim3(DMODEL * DMODEL / (256 * 4), 4), 256>>>(wc);

    // 2. QKV projections (batched)
    G3 pq;
    pq.A[0] = queries; pq.A[1] = keys; pq.A[2] = values;
    pq.W[0] = wq;      pq.W[1] = wk;   pq.W[2] = wv;
    pq.B[0] = bq;      pq.B[1] = bk;   pq.B[2] = bv;
    pq.C[0] = q;       pq.C[1] = k;    pq.C[2] = v;
    gemm_tf32_kernel<<<dim3(GEMM_N / 128, MTOT / 128, 3), 256, GEMM_SMEM_BYTES>>>(pq);

    // 3. attention
    attn_mma_kernel<<<dim3(LSEQ / 128, BATCH * NHEAD), 256, ATTN_SMEM_BYTES>>>(q, k, v, attn);

    // 4. output projection
    G3 po;
    po.A[0] = attn; po.W[0] = wo; po.B[0] = bo; po.C[0] = out;
    po.A[1] = po.A[2] = attn; po.W[1] = po.W[2] = wo;
    po.B[1] = po.B[2] = bo;   po.C[1] = po.C[2] = out;
    gemm_tf32_kernel<<<dim3(GEMM_N / 128, MTOT / 128, 1), 256, GEMM_SMEM_BYTES>>>(po);
}